// round 7
// baseline (speedup 1.0000x reference)
#include <cuda_runtime.h>
#include <cuda_bf16.h>
#include <cstdint>

// ----------------------------------------------------------------------------
// CrossAttention: split-bf16 (3-MMA) on mma.sync HMMA. This round: break the
// accumulator dependency chains (non-volatile MMA + split-outermost ordering).
// ----------------------------------------------------------------------------

namespace {
constexpr int NTOK = 16384;
constexpr int DMODEL = 512;
constexpr int NELEM = NTOK * DMODEL;
constexpr int WELEM = DMODEL * DMODEL;

constexpr int APAD = 40;
constexpr int BPAD = 136;
constexpr int ASZ = 128 * APAD;
constexpr int BSZ = 32 * BPAD;
constexpr int STG = 2 * ASZ + 2 * BSZ;
constexpr int SMEM_DENSE = 2 * STG * 2;          // 75776 bytes

constexpr int FARR = 64 * 72;
constexpr int FSTG = 4 * FARR;
constexpr int SMEM_FLASH = 2 * FSTG * 2;         // 73728 bytes
}

__device__ __nv_bfloat16 g_qh[NELEM],  g_ql[NELEM];
__device__ __nv_bfloat16 g_kvh[NELEM], g_kvl[NELEM];
__device__ __nv_bfloat16 g_wh[4 * WELEM], g_wl[4 * WELEM];
__device__ __nv_bfloat16 g_Qh[NELEM], g_Ql[NELEM];
__device__ __nv_bfloat16 g_Kh[NELEM], g_Kl[NELEM];
__device__ __nv_bfloat16 g_Vh[NELEM], g_Vl[NELEM];
__device__ __nv_bfloat16 g_Oh[NELEM], g_Ol[NELEM];

// NOTE: not volatile — pure register math, lets NVVM/ptxas interleave
// independent MMAs across accumulators.
__device__ __forceinline__ void mma16816(float* d, const unsigned* a, const unsigned* b) {
    asm("mma.sync.aligned.m16n8k16.row.col.f32.bf16.bf16.f32 "
        "{%0,%1,%2,%3},{%4,%5,%6,%7},{%8,%9},{%0,%1,%2,%3};\n"
        : "+f"(d[0]), "+f"(d[1]), "+f"(d[2]), "+f"(d[3])
        : "r"(a[0]), "r"(a[1]), "r"(a[2]), "r"(a[3]), "r"(b[0]), "r"(b[1]));
}
__device__ __forceinline__ unsigned smem_u32(const void* p) {
    return (unsigned)__cvta_generic_to_shared(p);
}
__device__ __forceinline__ void ldsm_x4(unsigned* r, unsigned addr) {
    asm volatile("ldmatrix.sync.aligned.m8n8.x4.shared.b16 {%0,%1,%2,%3}, [%4];"
                 : "=r"(r[0]), "=r"(r[1]), "=r"(r[2]), "=r"(r[3]) : "r"(addr));
}
__device__ __forceinline__ void ldsm_x4_t(unsigned* r, unsigned addr) {
    asm volatile("ldmatrix.sync.aligned.m8n8.x4.trans.shared.b16 {%0,%1,%2,%3}, [%4];"
                 : "=r"(r[0]), "=r"(r[1]), "=r"(r[2]), "=r"(r[3]) : "r"(addr));
}
__device__ __forceinline__ void cp16(unsigned dst, const void* src) {
    asm volatile("cp.async.cg.shared.global [%0], [%1], 16;\n" :: "r"(dst), "l"(src));
}
__device__ __forceinline__ void cp_commit() { asm volatile("cp.async.commit_group;\n" ::: "memory"); }
__device__ __forceinline__ void cp_wait0()  { asm volatile("cp.async.wait_group 0;\n" ::: "memory"); }
__device__ __forceinline__ void cp_wait1()  { asm volatile("cp.async.wait_group 1;\n" ::: "memory"); }

__device__ __forceinline__ unsigned pack2(__nv_bfloat16 x, __nv_bfloat16 y) {
    __nv_bfloat162 t{x, y};
    return *reinterpret_cast<unsigned*>(&t);
}
__device__ __forceinline__ void split_pack2(float x, float y, unsigned& hp, unsigned& lp) {
    __nv_bfloat16 hx = __float2bfloat16(x), hy = __float2bfloat16(y);
    __nv_bfloat16 lx = __float2bfloat16(x - __bfloat162float(hx));
    __nv_bfloat16 ly = __float2bfloat16(y - __bfloat162float(hy));
    hp = pack2(hx, hy);
    lp = pack2(lx, ly);
}

__global__ __launch_bounds__(256)
void split_kernel(const float* __restrict__ src, __nv_bfloat16* __restrict__ dh,
                  __nv_bfloat16* __restrict__ dl, int n4)
{
    int i = blockIdx.x * blockDim.x + threadIdx.x;
    if (i >= n4) return;
    float4 v = reinterpret_cast<const float4*>(src)[i];
    unsigned h01, l01, h23, l23;
    split_pack2(v.x, v.y, h01, l01);
    split_pack2(v.z, v.w, h23, l23);
    uint2 hv{h01, h23}, lv{l01, l23};
    reinterpret_cast<uint2*>(dh)[i] = hv;
    reinterpret_cast<uint2*>(dl)[i] = lv;
}

__global__ __launch_bounds__(256)
void split4_kernel(const float* __restrict__ W0, const float* __restrict__ W1,
                   const float* __restrict__ W2, const float* __restrict__ W3,
                   __nv_bfloat16* __restrict__ dh, __nv_bfloat16* __restrict__ dl)
{
    const int z = blockIdx.z;
    const float* src = (z == 0) ? W0 : (z == 1) ? W1 : (z == 2) ? W2 : W3;
    __nv_bfloat16* h = dh + (size_t)z * WELEM;
    __nv_bfloat16* l = dl + (size_t)z * WELEM;
    int i = blockIdx.x * blockDim.x + threadIdx.x;
    if (i >= WELEM / 4) return;
    float4 v = reinterpret_cast<const float4*>(src)[i];
    unsigned h01, l01, h23, l23;
    split_pack2(v.x, v.y, h01, l01);
    split_pack2(v.z, v.w, h23, l23);
    uint2 hv{h01, h23}, lv{l01, l23};
    reinterpret_cast<uint2*>(h)[i] = hv;
    reinterpret_cast<uint2*>(l)[i] = lv;
}

// ----------------------------------------------------------------------------
// Dense GEMM: 128x128 tile, BK=32, 8 warps (2x4), cp.async double buffer,
// ldmatrix fragments, split-outermost MMA ordering.
// ----------------------------------------------------------------------------
template <int OUT_SPLIT>
__global__ __launch_bounds__(256)
void gemm_bf16_kernel(const __nv_bfloat16* __restrict__ Ah, const __nv_bfloat16* __restrict__ Al,
                      const __nv_bfloat16* __restrict__ Bh, const __nv_bfloat16* __restrict__ Bl,
                      float* __restrict__ Cf,
                      __nv_bfloat16* __restrict__ Ch, __nv_bfloat16* __restrict__ Cl,
                      const float* __restrict__ bias, float alpha)
{
    extern __shared__ __nv_bfloat16 sm[];

    const int tid  = threadIdx.x;
    const int lane = tid & 31, warp = tid >> 5;
    const int wm = warp >> 2, wn = warp & 3;
    const int g  = lane >> 2, tg = lane & 3;
    const int lrow = lane & 7, lsel = lane >> 3;
    const int blockM = blockIdx.y * 128, blockN = blockIdx.x * 128;

    const int arow = tid >> 2, acol = (tid & 3) * 8;
    const int brow = tid >> 4, bcol = (tid & 15) * 8;

    float acc[4][4][4];
    #pragma unroll
    for (int mt = 0; mt < 4; mt++)
        #pragma unroll
        for (int nt = 0; nt < 4; nt++)
            #pragma unroll
            for (int i = 0; i < 4; i++) acc[mt][nt][i] = 0.f;

    auto load_tile = [&](int kt, int s) {
        __nv_bfloat16* base = sm + s * STG;
        #pragma unroll
        for (int j = 0; j < 2; j++) {
            const int r = arow + j * 64;
            const size_t go = (size_t)(blockM + r) * 512 + kt * 32 + acol;
            cp16(smem_u32(base + r * APAD + acol),       Ah + go);
            cp16(smem_u32(base + ASZ + r * APAD + acol), Al + go);
        }
        #pragma unroll
        for (int j = 0; j < 2; j++) {
            const int k = brow + j * 16;
            const size_t go = (size_t)(kt * 32 + k) * 512 + blockN + bcol;
            cp16(smem_u32(base + 2 * ASZ + k * BPAD + bcol),       Bh + go);
            cp16(smem_u32(base + 2 * ASZ + BSZ + k * BPAD + bcol), Bl + go);
        }
    };

    load_tile(0, 0);
    cp_commit();

    int buf = 0;
    for (int kt = 0; kt < 16; kt++) {
        cp_wait0();
        __syncthreads();
        if (kt < 15) { load_tile(kt + 1, buf ^ 1); cp_commit(); }

        const __nv_bfloat16* base = sm + buf * STG;
        #pragma unroll
        for (int kk = 0; kk < 32; kk += 16) {
            unsigned ah[4][4], al[4][4], bh[2][4], bl[2][4];
            #pragma unroll
            for (int mt = 0; mt < 4; mt++) {
                const int r0 = wm * 64 + mt * 16;
                const unsigned ea = smem_u32(base + (r0 + (lsel & 1) * 8 + lrow) * APAD
                                             + kk + (lsel >> 1) * 8);
                ldsm_x4(ah[mt], ea);
                ldsm_x4(al[mt], ea + ASZ * 2);
            }
            #pragma unroll
            for (int ntp = 0; ntp < 2; ntp++) {
                const int n0 = wn * 32 + ntp * 16;
                const unsigned eb = smem_u32(base + 2 * ASZ
                                             + (kk + (lsel & 1) * 8 + lrow) * BPAD
                                             + n0 + (lsel >> 1) * 8);
                ldsm_x4_t(bh[ntp], eb);
                ldsm_x4_t(bl[ntp], eb + BSZ * 2);
            }
            // pass 1: hi*hi — 16 independent accumulators
            #pragma unroll
            for (int mt = 0; mt < 4; mt++)
                #pragma unroll
                for (int nt = 0; nt < 4; nt++)
                    mma16816(acc[mt][nt], ah[mt], &bh[nt >> 1][(nt & 1) * 2]);
            // pass 2: hi*lo
            #pragma unroll
            for (int mt = 0; mt < 4; mt++)
                #pragma unroll
                for (int nt = 0; nt < 4; nt++)
                    mma16816(acc[mt][nt], ah[mt], &bl[nt >> 1][(nt & 1) * 2]);
            // pass 3: lo*hi
            #pragma unroll
            for (int mt = 0; mt < 4; mt++)
                #pragma unroll
                for (int nt = 0; nt < 4; nt++)
                    mma16816(acc[mt][nt], al[mt], &bh[nt >> 1][(nt & 1) * 2]);
        }
        buf ^= 1;
    }

    #pragma unroll
    for (int mt = 0; mt < 4; mt++)
        #pragma unroll
        for (int nt = 0; nt < 4; nt++) {
            const int r  = blockM + wm * 64 + mt * 16 + g;
            const int cc = blockN + wn * 32 + nt * 8 + tg * 2;
            const float v0 = alpha * acc[mt][nt][0];
            const float v1 = alpha * acc[mt][nt][1];
            const float v2 = alpha * acc[mt][nt][2];
            const float v3 = alpha * acc[mt][nt][3];
            if (OUT_SPLIT) {
                unsigned hp, lp;
                split_pack2(v0, v1, hp, lp);
                *(unsigned*)&Ch[(size_t)r * 512 + cc] = hp;
                *(unsigned*)&Cl[(size_t)r * 512 + cc] = lp;
                split_pack2(v2, v3, hp, lp);
                *(unsigned*)&Ch[(size_t)(r + 8) * 512 + cc] = hp;
                *(unsigned*)&Cl[(size_t)(r + 8) * 512 + cc] = lp;
            } else {
                const float b0 = bias[cc], b1 = bias[cc + 1];
                Cf[(size_t)r * 512 + cc]           = v0 + b0;
                Cf[(size_t)r * 512 + cc + 1]       = v1 + b1;
                Cf[(size_t)(r + 8) * 512 + cc]     = v2 + b0;
                Cf[(size_t)(r + 8) * 512 + cc + 1] = v3 + b1;
            }
        }
}

// ----------------------------------------------------------------------------
// Flash attention, cp.async double-buffered; MMA splits interleaved across
// accumulator pairs.
// ----------------------------------------------------------------------------
__global__ __launch_bounds__(256)
void flash_kernel(const __nv_bfloat16* __restrict__ Qh, const __nv_bfloat16* __restrict__ Ql,
                  const __nv_bfloat16* __restrict__ Kh, const __nv_bfloat16* __restrict__ Kl,
                  const __nv_bfloat16* __restrict__ Vh, const __nv_bfloat16* __restrict__ Vl,
                  __nv_bfloat16* __restrict__ Oh, __nv_bfloat16* __restrict__ Ol)
{
    extern __shared__ __nv_bfloat16 fsm[];

    const int z = blockIdx.y;
    const long long zo = z >> 3, zi = z & 7;
    const size_t gbase = (size_t)zo * 512 * 512 + (size_t)zi * 64;

    const int tid  = threadIdx.x;
    const int lane = tid & 31, warp = tid >> 5;
    const int g = lane >> 2, tg = lane & 3;
    const int lrow = lane & 7, lsel = lane >> 3;
    const int rowA = blockIdx.x * 128 + warp * 16 + g;

    unsigned qh[4][4], ql[4][4];
    #pragma unroll
    for (int kc = 0; kc < 4; kc++) {
        const int c = kc * 16 + tg * 2;
        qh[kc][0] = *(const unsigned*)&Qh[gbase + (size_t)rowA * 512 + c];
        qh[kc][1] = *(const unsigned*)&Qh[gbase + (size_t)(rowA + 8) * 512 + c];
        qh[kc][2] = *(const unsigned*)&Qh[gbase + (size_t)rowA * 512 + c + 8];
        qh[kc][3] = *(const unsigned*)&Qh[gbase + (size_t)(rowA + 8) * 512 + c + 8];
        ql[kc][0] = *(const unsigned*)&Ql[gbase + (size_t)rowA * 512 + c];
        ql[kc][1] = *(const unsigned*)&Ql[gbase + (size_t)(rowA + 8) * 512 + c];
        ql[kc][2] = *(const unsigned*)&Ql[gbase + (size_t)rowA * 512 + c + 8];
        ql[kc][3] = *(const unsigned*)&Ql[gbase + (size_t)(rowA + 8) * 512 + c + 8];
    }

    auto load_kv = [&](int kt, int s) {
        __nv_bfloat16* st = fsm + s * FSTG;
        #pragma unroll
        for (int j = 0; j < 2; j++) {
            const int idx = tid + j * 256;
            const int row = idx >> 3, q = (idx & 7) * 8;
            const size_t go = gbase + (size_t)(kt * 64 + row) * 512 + q;
            const unsigned so = row * 72 + q;
            cp16(smem_u32(st + so),            Kh + go);
            cp16(smem_u32(st + FARR + so),     Kl + go);
            cp16(smem_u32(st + 2 * FARR + so), Vh + go);
            cp16(smem_u32(st + 3 * FARR + so), Vl + go);
        }
    };

    float o[8][4];
    #pragma unroll
    for (int nd = 0; nd < 8; nd++)
        #pragma unroll
        for (int i = 0; i < 4; i++) o[nd][i] = 0.f;
    float m0 = -1e30f, m1 = -1e30f, l0 = 0.f, l1 = 0.f;

    load_kv(0, 0); cp_commit();
    load_kv(1, 1); cp_commit();

    for (int kt = 0; kt < 8; kt++) {
        const int s = kt & 1;
        if (kt < 7) cp_wait1(); else cp_wait0();
        __syncthreads();

        const __nv_bfloat16* sKh = fsm + s * FSTG;
        const __nv_bfloat16* sKl = sKh + FARR;
        const __nv_bfloat16* sVh = sKh + 2 * FARR;
        const __nv_bfloat16* sVl = sKh + 3 * FARR;

        float sx[8][4];
        #pragma unroll
        for (int nt = 0; nt < 8; nt++)
            #pragma unroll
            for (int i = 0; i < 4; i++) sx[nt][i] = 0.f;

        #pragma unroll
        for (int kc = 0; kc < 4; kc++) {
            const int c0 = kc * 16;
            #pragma unroll
            for (int ntp = 0; ntp < 4; ntp++) {
                const int n0 = ntp * 16;
                unsigned bh4[4], bl4[4];
                const unsigned ea = smem_u32(sKh + (n0 + (lsel >> 1) * 8 + lrow) * 72 + c0 + (lsel & 1) * 8);
                const unsigned el = smem_u32(sKl + (n0 + (lsel >> 1) * 8 + lrow) * 72 + c0 + (lsel & 1) * 8);
                ldsm_x4(bh4, ea);
                ldsm_x4(bl4, el);
                // interleave splits across the two accumulators
                mma16816(sx[2 * ntp],     qh[kc], bh4);
                mma16816(sx[2 * ntp + 1], qh[kc], bh4 + 2);
                mma16816(sx[2 * ntp],     qh[kc], bl4);
                mma16816(sx[2 * ntp + 1], qh[kc], bl4 + 2);
                mma16816(sx[2 * ntp],     ql[kc], bh4);
                mma16816(sx[2 * ntp + 1], ql[kc], bh4 + 2);
            }
        }

        float r0 = -1e30f, r1 = -1e30f;
        #pragma unroll
        for (int nt = 0; nt < 8; nt++) {
            r0 = fmaxf(r0, fmaxf(sx[nt][0], sx[nt][1]));
            r1 = fmaxf(r1, fmaxf(sx[nt][2], sx[nt][3]));
        }
        r0 = fmaxf(r0, __shfl_xor_sync(0xffffffffu, r0, 1));
        r0 = fmaxf(r0, __shfl_xor_sync(0xffffffffu, r0, 2));
        r1 = fmaxf(r1, __shfl_xor_sync(0xffffffffu, r1, 1));
        r1 = fmaxf(r1, __shfl_xor_sync(0xffffffffu, r1, 2));
        const float m0n = fmaxf(m0, r0), m1n = fmaxf(m1, r1);
        const float a0 = __expf(m0 - m0n), a1 = __expf(m1 - m1n);

        float ps0 = 0.f, ps1 = 0.f;
        #pragma unroll
        for (int nt = 0; nt < 8; nt++) {
            sx[nt][0] = __expf(sx[nt][0] - m0n);
            sx[nt][1] = __expf(sx[nt][1] - m0n);
            sx[nt][2] = __expf(sx[nt][2] - m1n);
            sx[nt][3] = __expf(sx[nt][3] - m1n);
            ps0 += sx[nt][0] + sx[nt][1];
            ps1 += sx[nt][2] + sx[nt][3];
        }
        m0 = m0n; m1 = m1n;
        l0 = l0 * a0 + ps0;
        l1 = l1 * a1 + ps1;
        #pragma unroll
        for (int nd = 0; nd < 8; nd++) {
            o[nd][0] *= a0; o[nd][1] *= a0;
            o[nd][2] *= a1; o[nd][3] *= a1;
        }

        #pragma unroll
        for (int kc = 0; kc < 4; kc++) {
            const int c0 = kc * 16;
            unsigned pah[4], pal[4];
            split_pack2(sx[2 * kc][0],     sx[2 * kc][1],     pah[0], pal[0]);
            split_pack2(sx[2 * kc][2],     sx[2 * kc][3],     pah[1], pal[1]);
            split_pack2(sx[2 * kc + 1][0], sx[2 * kc + 1][1], pah[2], pal[2]);
            split_pack2(sx[2 * kc + 1][2], sx[2 * kc + 1][3], pah[3], pal[3]);
            #pragma unroll
            for (int ndp = 0; ndp < 4; ndp++) {
                const int d0 = ndp * 16;
                unsigned vh4[4], vl4[4];
                const unsigned ea = smem_u32(sVh + (c0 + (lsel & 1) * 8 + lrow) * 72 + d0 + (lsel >> 1) * 8);
                const unsigned el = smem_u32(sVl + (c0 + (lsel & 1) * 8 + lrow) * 72 + d0 + (lsel >> 1) * 8);
                ldsm_x4_t(vh4, ea);
                ldsm_x4_t(vl4, el);
                mma16816(o[2 * ndp],     pah, vh4);
                mma16816(o[2 * ndp + 1], pah, vh4 + 2);
                mma16816(o[2 * ndp],     pah, vl4);
                mma16816(o[2 * ndp + 1], pah, vl4 + 2);
                mma16816(o[2 * ndp],     pal, vh4);
                mma16816(o[2 * ndp + 1], pal, vh4 + 2);
            }
        }
        __syncthreads();
        if (kt + 2 < 8) { load_kv(kt + 2, s); cp_commit(); }
    }

    l0 += __shfl_xor_sync(0xffffffffu, l0, 1);
    l0 += __shfl_xor_sync(0xffffffffu, l0, 2);
    l1 += __shfl_xor_sync(0xffffffffu, l1, 1);
    l1 += __shfl_xor_sync(0xffffffffu, l1, 2);
    const float inv0 = 1.f / l0, inv1 = 1.f / l1;

    #pragma unroll
    for (int nd = 0; nd < 8; nd++) {
        const int cc = nd * 8 + tg * 2;
        unsigned hp, lp;
        split_pack2(o[nd][0] * inv0, o[nd][1] * inv0, hp, lp);
        *(unsigned*)&Oh[gbase + (size_t)rowA * 512 + cc] = hp;
        *(unsigned*)&Ol[gbase + (size_t)rowA * 512 + cc] = lp;
        split_pack2(o[nd][2] * inv1, o[nd][3] * inv1, hp, lp);
        *(unsigned*)&Oh[gbase + (size_t)(rowA + 8) * 512 + cc] = hp;
        *(unsigned*)&Ol[gbase + (size_t)(rowA + 8) * 512 + cc] = lp;
    }
}

extern "C" void kernel_launch(void* const* d_in, const int* in_sizes, int n_in,
                              void* d_out, int out_size)
{
    const float* q_in  = (const float*)d_in[0];
    const float* kv_in = (const float*)d_in[1];
    const float* Wq    = (const float*)d_in[2];
    const float* Wk    = (const float*)d_in[3];
    const float* Wv    = (const float*)d_in[4];
    const float* Wo    = (const float*)d_in[5];
    const float* bo    = (const float*)d_in[6];
    float* out = (float*)d_out;

    __nv_bfloat16 *qh, *ql, *kvh, *kvl, *wh, *wl;
    __nv_bfloat16 *Qh, *Ql, *Kh, *Kl, *Vh, *Vl, *Oh, *Ol;
    cudaGetSymbolAddress((void**)&qh,  g_qh);  cudaGetSymbolAddress((void**)&ql,  g_ql);
    cudaGetSymbolAddress((void**)&kvh, g_kvh); cudaGetSymbolAddress((void**)&kvl, g_kvl);
    cudaGetSymbolAddress((void**)&wh,  g_wh);  cudaGetSymbolAddress((void**)&wl,  g_wl);
    cudaGetSymbolAddress((void**)&Qh,  g_Qh);  cudaGetSymbolAddress((void**)&Ql,  g_Ql);
    cudaGetSymbolAddress((void**)&Kh,  g_Kh);  cudaGetSymbolAddress((void**)&Kl,  g_Kl);
    cudaGetSymbolAddress((void**)&Vh,  g_Vh);  cudaGetSymbolAddress((void**)&Vl,  g_Vl);
    cudaGetSymbolAddress((void**)&Oh,  g_Oh);  cudaGetSymbolAddress((void**)&Ol,  g_Ol);

    cudaFuncSetAttribute(gemm_bf16_kernel<1>, cudaFuncAttributeMaxDynamicSharedMemorySize, SMEM_DENSE);
    cudaFuncSetAttribute(gemm_bf16_kernel<0>, cudaFuncAttributeMaxDynamicSharedMemorySize, SMEM_DENSE);
    cudaFuncSetAttribute(flash_kernel,        cudaFuncAttributeMaxDynamicSharedMemorySize, SMEM_FLASH);

    const dim3 ggrid(512 / 128, NTOK / 128, 1);

    split_kernel<<<(NELEM / 4 + 255) / 256, 256>>>(q_in,  qh,  ql,  NELEM / 4);
    split_kernel<<<(NELEM / 4 + 255) / 256, 256>>>(kv_in, kvh, kvl, NELEM / 4);
    split4_kernel<<<dim3(WELEM / 4 / 256, 1, 4), 256>>>(Wq, Wk, Wv, Wo, wh, wl);

    gemm_bf16_kernel<1><<<ggrid, 256, SMEM_DENSE>>>(qh,  ql,  wh,             wl,             nullptr, Qh, Ql, nullptr, 0.125f);
    gemm_bf16_kernel<1><<<ggrid, 256, SMEM_DENSE>>>(kvh, kvl, wh + WELEM,     wl + WELEM,     nullptr, Kh, Kl, nullptr, 1.f);
    gemm_bf16_kernel<1><<<ggrid, 256, SMEM_DENSE>>>(kvh, kvl, wh + 2 * WELEM, wl + 2 * WELEM, nullptr, Vh, Vl, nullptr, 1.f);

    flash_kernel<<<dim3(4, 256), 256, SMEM_FLASH>>>(Qh, Ql, Kh, Kl, Vh, Vl, Oh, Ol);

    gemm_bf16_kernel<0><<<ggrid, 256, SMEM_DENSE>>>(Oh, Ol, wh + 3 * WELEM, wl + 3 * WELEM, out, nullptr, nullptr, bo, 1.f);
}

// round 10
// speedup vs baseline: 1.2016x; 1.2016x over previous
#include <cuda_runtime.h>
#include <cuda_fp16.h>
#include <cstdint>

// ----------------------------------------------------------------------------
// CrossAttention, fp16 2-MMA split scheme:
//   C = Ah*Bh + Ah*Bl   (A stored hi-only; dropped Al*Bh ~ 2^-12 rel)
// Dense GEMMs: 128x128 tile, BK=32, 3-stage cp.async, ldmatrix fragments.
// Flash: QK 3-term (Qh,Ql vs Kh,Kl), softmax scale post-MMA, PV 2-term
// (P single fp16, Vh+Vl), O stored hi-only.
// R9 fix: A tile load covers all 128 rows (R8 only loaded rows 0-63 -> NaN).
// ----------------------------------------------------------------------------

namespace {
constexpr int NTOK = 16384;
constexpr int DMODEL = 512;
constexpr int NELEM = NTOK * DMODEL;
constexpr int WELEM = DMODEL * DMODEL;
constexpr float SCALE = 0.125f;

constexpr int APAD = 40;
constexpr int BPAD = 136;
constexpr int ASZ = 128 * APAD;                  // 5120 (A hi only)
constexpr int BSZ = 32 * BPAD;                   // 4352
constexpr int STG = ASZ + 2 * BSZ;               // 13824 elems
constexpr int SMEM_DENSE = 3 * STG * 2;          // 82944 bytes (3 stages)

constexpr int FARR = 64 * 72;
constexpr int FSTG = 4 * FARR;                   // Kh|Kl|Vh|Vl
constexpr int SMEM_FLASH = 2 * FSTG * 2;         // 73728 bytes
}

__device__ __half g_qh[NELEM];                   // q_in  hi
__device__ __half g_kvh[NELEM];                  // kv_in hi
__device__ __half g_wh[4 * WELEM], g_wl[4 * WELEM];
__device__ __half g_Qh[NELEM], g_Ql[NELEM];
__device__ __half g_Kh[NELEM], g_Kl[NELEM];
__device__ __half g_Vh[NELEM], g_Vl[NELEM];
__device__ __half g_Oh[NELEM];

__device__ __forceinline__ void mma16816(float* d, const unsigned* a, const unsigned* b) {
    asm("mma.sync.aligned.m16n8k16.row.col.f32.f16.f16.f32 "
        "{%0,%1,%2,%3},{%4,%5,%6,%7},{%8,%9},{%0,%1,%2,%3};\n"
        : "+f"(d[0]), "+f"(d[1]), "+f"(d[2]), "+f"(d[3])
        : "r"(a[0]), "r"(a[1]), "r"(a[2]), "r"(a[3]), "r"(b[0]), "r"(b[1]));
}
__device__ __forceinline__ unsigned smem_u32(const void* p) {
    return (unsigned)__cvta_generic_to_shared(p);
}
__device__ __forceinline__ void ldsm_x4(unsigned* r, unsigned addr) {
    asm volatile("ldmatrix.sync.aligned.m8n8.x4.shared.b16 {%0,%1,%2,%3}, [%4];"
                 : "=r"(r[0]), "=r"(r[1]), "=r"(r[2]), "=r"(r[3]) : "r"(addr));
}
__device__ __forceinline__ void ldsm_x4_t(unsigned* r, unsigned addr) {
    asm volatile("ldmatrix.sync.aligned.m8n8.x4.trans.shared.b16 {%0,%1,%2,%3}, [%4];"
                 : "=r"(r[0]), "=r"(r[1]), "=r"(r[2]), "=r"(r[3]) : "r"(addr));
}
__device__ __forceinline__ void cp16(unsigned dst, const void* src) {
    asm volatile("cp.async.cg.shared.global [%0], [%1], 16;\n" :: "r"(dst), "l"(src));
}
__device__ __forceinline__ void cp_commit() { asm volatile("cp.async.commit_group;\n" ::: "memory"); }
__device__ __forceinline__ void cp_wait0()  { asm volatile("cp.async.wait_group 0;\n" ::: "memory"); }
__device__ __forceinline__ void cp_wait1()  { asm volatile("cp.async.wait_group 1;\n" ::: "memory"); }

__device__ __forceinline__ unsigned pack2h(__half x, __half y) {
    __half2 t = __halves2half2(x, y);
    return *reinterpret_cast<unsigned*>(&t);
}
__device__ __forceinline__ void split_pack2h(float x, float y, unsigned& hp, unsigned& lp) {
    __half hx = __float2half(x), hy = __float2half(y);
    __half lx = __float2half(x - __half2float(hx));
    __half ly = __float2half(y - __half2float(hy));
    hp = pack2h(hx, hy);
    lp = pack2h(lx, ly);
}

// fp32 -> fp16 (hi only), 4 elems/thread
__global__ __launch_bounds__(256)
void cvt_kernel(const float* __restrict__ src, __half* __restrict__ dh, int n4)
{
    int i = blockIdx.x * blockDim.x + threadIdx.x;
    if (i >= n4) return;
    float4 v = reinterpret_cast<const float4*>(src)[i];
    unsigned h01 = pack2h(__float2half(v.x), __float2half(v.y));
    unsigned h23 = pack2h(__float2half(v.z), __float2half(v.w));
    uint2 hv{h01, h23};
    reinterpret_cast<uint2*>(dh)[i] = hv;
}

// weights: fp32 -> fp16 hi + lo; z selects weight
__global__ __launch_bounds__(256)
void split4_kernel(const float* __restrict__ W0, const float* __restrict__ W1,
                   const float* __restrict__ W2, const float* __restrict__ W3,
                   __half* __restrict__ dh, __half* __restrict__ dl)
{
    const int z = blockIdx.z;
    const float* src = (z == 0) ? W0 : (z == 1) ? W1 : (z == 2) ? W2 : W3;
    __half* h = dh + (size_t)z * WELEM;
    __half* l = dl + (size_t)z * WELEM;
    int i = blockIdx.x * blockDim.x + threadIdx.x;
    if (i >= WELEM / 4) return;
    float4 v = reinterpret_cast<const float4*>(src)[i];
    unsigned h01, l01, h23, l23;
    split_pack2h(v.x, v.y, h01, l01);
    split_pack2h(v.z, v.w, h23, l23);
    uint2 hv{h01, h23}, lv{l01, l23};
    reinterpret_cast<uint2*>(h)[i] = hv;
    reinterpret_cast<uint2*>(l)[i] = lv;
}

// ----------------------------------------------------------------------------
// Dense GEMM: C = alpha*(Ah@Bh + Ah@Bl) (+bias). A [16384x512] fp16 hi,
// B [512x512] fp16 hi+lo. 128x128 tile, BK=32, 3-stage cp.async.
// OUT_SPLIT=1: write (Ch, Cl) fp16; else fp32 + bias.
// ----------------------------------------------------------------------------
template <int OUT_SPLIT>
__global__ __launch_bounds__(256)
void gemm_fp16_kernel(const __half* __restrict__ Ah,
                      const __half* __restrict__ Bh, const __half* __restrict__ Bl,
                      float* __restrict__ Cf,
                      __half* __restrict__ Ch, __half* __restrict__ Cl,
                      const float* __restrict__ bias, float alpha)
{
    extern __shared__ __half sm[];

    const int tid  = threadIdx.x;
    const int lane = tid & 31, warp = tid >> 5;
    const int wm = warp >> 2, wn = warp & 3;
    const int g  = lane >> 2, tg = lane & 3;
    const int lrow = lane & 7, lsel = lane >> 3;
    const int blockM = blockIdx.y * 128, blockN = blockIdx.x * 128;

    const int arow = tid >> 2, acol = (tid & 3) * 8;   // A: rows arow + j*64
    const int brow = tid >> 4, bcol = (tid & 15) * 8;  // B: 32 rows x 128 halves

    float acc[4][4][4];
    #pragma unroll
    for (int mt = 0; mt < 4; mt++)
        #pragma unroll
        for (int nt = 0; nt < 4; nt++)
            #pragma unroll
            for (int i = 0; i < 4; i++) acc[mt][nt][i] = 0.f;

    auto load_tile = [&](int kt, int s) {
        __half* base = sm + s * STG;
        // A hi: 128 rows x 64B  (R9 FIX: both 64-row halves)
        #pragma unroll
        for (int j = 0; j < 2; j++) {
            const int r = arow + j * 64;
            const size_t go = (size_t)(blockM + r) * 512 + kt * 32 + acol;
            cp16(smem_u32(base + r * APAD + acol), Ah + go);
        }
        // B hi + lo: 32 rows x 256B each
        #pragma unroll
        for (int j = 0; j < 2; j++) {
            const int k = brow + j * 16;
            const size_t go = (size_t)(kt * 32 + k) * 512 + blockN + bcol;
            cp16(smem_u32(base + ASZ + k * BPAD + bcol),       Bh + go);
            cp16(smem_u32(base + ASZ + BSZ + k * BPAD + bcol), Bl + go);
        }
    };

    load_tile(0, 0); cp_commit();
    load_tile(1, 1); cp_commit();

    for (int kt = 0; kt < 16; kt++) {
        const int s = kt % 3;
        if (kt == 15) cp_wait0(); else cp_wait1();
        __syncthreads();
        if (kt + 2 < 16) { load_tile(kt + 2, (kt + 2) % 3); cp_commit(); }

        const __half* base = sm + s * STG;
        #pragma unroll
        for (int kk = 0; kk < 32; kk += 16) {
            unsigned ah[4][4], bh[2][4], bl[2][4];
            #pragma unroll
            for (int mt = 0; mt < 4; mt++) {
                const int r0 = wm * 64 + mt * 16;
                const unsigned ea = smem_u32(base + (r0 + (lsel & 1) * 8 + lrow) * APAD
                                             + kk + (lsel >> 1) * 8);
                ldsm_x4(ah[mt], ea);
            }
            #pragma unroll
            for (int ntp = 0; ntp < 2; ntp++) {
                const int n0 = wn * 32 + ntp * 16;
                const unsigned eb = smem_u32(base + ASZ
                                             + (kk + (lsel & 1) * 8 + lrow) * BPAD
                                             + n0 + (lsel >> 1) * 8);
                ldsm_x4_t(bh[ntp], eb);
                ldsm_x4_t(bl[ntp], eb + BSZ * 2);
            }
            // pass 1: Ah*Bh
            #pragma unroll
            for (int mt = 0; mt < 4; mt++)
                #pragma unroll
                for (int nt = 0; nt < 4; nt++)
                    mma16816(acc[mt][nt], ah[mt], &bh[nt >> 1][(nt & 1) * 2]);
            // pass 2: Ah*Bl
            #pragma unroll
            for (int mt = 0; mt < 4; mt++)
                #pragma unroll
                for (int nt = 0; nt < 4; nt++)
                    mma16816(acc[mt][nt], ah[mt], &bl[nt >> 1][(nt & 1) * 2]);
        }
    }

    #pragma unroll
    for (int mt = 0; mt < 4; mt++)
        #pragma unroll
        for (int nt = 0; nt < 4; nt++) {
            const int r  = blockM + wm * 64 + mt * 16 + g;
            const int cc = blockN + wn * 32 + nt * 8 + tg * 2;
            const float v0 = alpha * acc[mt][nt][0];
            const float v1 = alpha * acc[mt][nt][1];
            const float v2 = alpha * acc[mt][nt][2];
            const float v3 = alpha * acc[mt][nt][3];
            if (OUT_SPLIT) {
                unsigned hp, lp;
                split_pack2h(v0, v1, hp, lp);
                *(unsigned*)&Ch[(size_t)r * 512 + cc] = hp;
                *(unsigned*)&Cl[(size_t)r * 512 + cc] = lp;
                split_pack2h(v2, v3, hp, lp);
                *(unsigned*)&Ch[(size_t)(r + 8) * 512 + cc] = hp;
                *(unsigned*)&Cl[(size_t)(r + 8) * 512 + cc] = lp;
            } else {
                const float b0 = bias[cc], b1 = bias[cc + 1];
                Cf[(size_t)r * 512 + cc]           = v0 + b0;
                Cf[(size_t)r * 512 + cc + 1]       = v1 + b1;
                Cf[(size_t)(r + 8) * 512 + cc]     = v2 + b0;
                Cf[(size_t)(r + 8) * 512 + cc + 1] = v3 + b1;
            }
        }
}

// ----------------------------------------------------------------------------
// Flash attention: QK 3-term, post-MMA scale, PV 2-term, O hi-only.
// cp.async double-buffered K/V staging.
// ----------------------------------------------------------------------------
__global__ __launch_bounds__(256)
void flash_kernel(const __half* __restrict__ Qh, const __half* __restrict__ Ql,
                  const __half* __restrict__ Kh, const __half* __restrict__ Kl,
                  const __half* __restrict__ Vh, const __half* __restrict__ Vl,
                  __half* __restrict__ Oh)
{
    extern __shared__ __half fsm[];

    const int z = blockIdx.y;
    const long long zo = z >> 3, zi = z & 7;
    const size_t gbase = (size_t)zo * 512 * 512 + (size_t)zi * 64;

    const int tid  = threadIdx.x;
    const int lane = tid & 31, warp = tid >> 5;
    const int g = lane >> 2, tg = lane & 3;
    const int lrow = lane & 7, lsel = lane >> 3;
    const int rowA = blockIdx.x * 128 + warp * 16 + g;

    unsigned qh[4][4], ql[4][4];
    #pragma unroll
    for (int kc = 0; kc < 4; kc++) {
        const int c = kc * 16 + tg * 2;
        qh[kc][0] = *(const unsigned*)&Qh[gbase + (size_t)rowA * 512 + c];
        qh[kc][1] = *(const unsigned*)&Qh[gbase + (size_t)(rowA + 8) * 512 + c];
        qh[kc][2] = *(const unsigned*)&Qh[gbase + (size_t)rowA * 512 + c + 8];
        qh[kc][3] = *(const unsigned*)&Qh[gbase + (size_t)(rowA + 8) * 512 + c + 8];
        ql[kc][0] = *(const unsigned*)&Ql[gbase + (size_t)rowA * 512 + c];
        ql[kc][1] = *(const unsigned*)&Ql[gbase + (size_t)(rowA + 8) * 512 + c];
        ql[kc][2] = *(const unsigned*)&Ql[gbase + (size_t)rowA * 512 + c + 8];
        ql[kc][3] = *(const unsigned*)&Ql[gbase + (size_t)(rowA + 8) * 512 + c + 8];
    }

    auto load_kv = [&](int kt, int s) {
        __half* st = fsm + s * FSTG;
        #pragma unroll
        for (int j = 0; j < 2; j++) {
            const int idx = tid + j * 256;
            const int row = idx >> 3, q = (idx & 7) * 8;
            const size_t go = gbase + (size_t)(kt * 64 + row) * 512 + q;
            const unsigned so = row * 72 + q;
            cp16(smem_u32(st + so),            Kh + go);
            cp16(smem_u32(st + FARR + so),     Kl + go);
            cp16(smem_u32(st + 2 * FARR + so), Vh + go);
            cp16(smem_u32(st + 3 * FARR + so), Vl + go);
        }
    };

    float o[8][4];
    #pragma unroll
    for (int nd = 0; nd < 8; nd++)
        #pragma unroll
        for (int i = 0; i < 4; i++) o[nd][i] = 0.f;
    float m0 = -1e30f, m1 = -1e30f, l0 = 0.f, l1 = 0.f;

    load_kv(0, 0); cp_commit();
    load_kv(1, 1); cp_commit();

    for (int kt = 0; kt < 8; kt++) {
        const int s = kt & 1;
        if (kt < 7) cp_wait1(); else cp_wait0();
        __syncthreads();

        const __half* sKh = fsm + s * FSTG;
        const __half* sKl = sKh + FARR;
        const __half* sVh = sKh + 2 * FARR;
        const __half* sVl = sKh + 3 * FARR;

        float sx[8][4];
        #pragma unroll
        for (int nt = 0; nt < 8; nt++)
            #pragma unroll
            for (int i = 0; i < 4; i++) sx[nt][i] = 0.f;

        #pragma unroll
        for (int kc = 0; kc < 4; kc++) {
            const int c0 = kc * 16;
            #pragma unroll
            for (int ntp = 0; ntp < 4; ntp++) {
                const int n0 = ntp * 16;
                unsigned bh4[4], bl4[4];
                const unsigned ea = smem_u32(sKh + (n0 + (lsel >> 1) * 8 + lrow) * 72 + c0 + (lsel & 1) * 8);
                const unsigned el = smem_u32(sKl + (n0 + (lsel >> 1) * 8 + lrow) * 72 + c0 + (lsel & 1) * 8);
                ldsm_x4(bh4, ea);
                ldsm_x4(bl4, el);
                mma16816(sx[2 * ntp],     qh[kc], bh4);
                mma16816(sx[2 * ntp + 1], qh[kc], bh4 + 2);
                mma16816(sx[2 * ntp],     qh[kc], bl4);
                mma16816(sx[2 * ntp + 1], qh[kc], bl4 + 2);
                mma16816(sx[2 * ntp],     ql[kc], bh4);
                mma16816(sx[2 * ntp + 1], ql[kc], bh4 + 2);
            }
        }

        // scale post-MMA (keeps Q-lo in fp16 normal range)
        #pragma unroll
        for (int nt = 0; nt < 8; nt++)
            #pragma unroll
            for (int i = 0; i < 4; i++) sx[nt][i] *= SCALE;

        float r0 = -1e30f, r1 = -1e30f;
        #pragma unroll
        for (int nt = 0; nt < 8; nt++) {
            r0 = fmaxf(r0, fmaxf(sx[nt][0], sx[nt][1]));
            r1 = fmaxf(r1, fmaxf(sx[nt][2], sx[nt][3]));
        }
        r0 = fmaxf(r0, __shfl_xor_sync(0xffffffffu, r0, 1));
        r0 = fmaxf(r0, __shfl_xor_sync(0xffffffffu, r0, 2));
        r1 = fmaxf(r1, __shfl_xor_sync(0xffffffffu, r1, 1));
        r1 = fmaxf(r1, __shfl_xor_sync(0xffffffffu, r1, 2));
        const float m0n = fmaxf(m0, r0), m1n = fmaxf(m1, r1);
        const float a0 = __expf(m0 - m0n), a1 = __expf(m1 - m1n);

        float ps0 = 0.f, ps1 = 0.f;
        #pragma unroll
        for (int nt = 0; nt < 8; nt++) {
            sx[nt][0] = __expf(sx[nt][0] - m0n);
            sx[nt][1] = __expf(sx[nt][1] - m0n);
            sx[nt][2] = __expf(sx[nt][2] - m1n);
            sx[nt][3] = __expf(sx[nt][3] - m1n);
            ps0 += sx[nt][0] + sx[nt][1];
            ps1 += sx[nt][2] + sx[nt][3];
        }
        m0 = m0n; m1 = m1n;
        l0 = l0 * a0 + ps0;
        l1 = l1 * a1 + ps1;
        #pragma unroll
        for (int nd = 0; nd < 8; nd++) {
            o[nd][0] *= a0; o[nd][1] *= a0;
            o[nd][2] *= a1; o[nd][3] *= a1;
        }

        // ---- O += P V (P single fp16, V hi+lo) ----
        #pragma unroll
        for (int kc = 0; kc < 4; kc++) {
            const int c0 = kc * 16;
            unsigned pa[4];
            pa[0] = pack2h(__float2half(sx[2 * kc][0]),     __float2half(sx[2 * kc][1]));
            pa[1] = pack2h(__float2half(sx[2 * kc][2]),     __float2half(sx[2 * kc][3]));
            pa[2] = pack2h(__float2half(sx[2 * kc + 1][0]), __float2half(sx[2 * kc + 1][1]));
            pa[3] = pack2h(__float2half(sx[2 * kc + 1][2]), __float2half(sx[2 * kc + 1][3]));
            #pragma unroll
            for (int ndp = 0; ndp < 4; ndp++) {
                const int d0 = ndp * 16;
                unsigned vh4[4], vl4[4];
                const unsigned ea = smem_u32(sVh + (c0 + (lsel & 1) * 8 + lrow) * 72 + d0 + (lsel >> 1) * 8);
                const unsigned el = smem_u32(sVl + (c0 + (lsel & 1) * 8 + lrow) * 72 + d0 + (lsel >> 1) * 8);
                ldsm_x4_t(vh4, ea);
                ldsm_x4_t(vl4, el);
                mma16816(o[2 * ndp],     pa, vh4);
                mma16816(o[2 * ndp + 1], pa, vh4 + 2);
                mma16816(o[2 * ndp],     pa, vl4);
                mma16816(o[2 * ndp + 1], pa, vl4 + 2);
            }
        }
        __syncthreads();
        if (kt + 2 < 8) { load_kv(kt + 2, s); cp_commit(); }
    }

    l0 += __shfl_xor_sync(0xffffffffu, l0, 1);
    l0 += __shfl_xor_sync(0xffffffffu, l0, 2);
    l1 += __shfl_xor_sync(0xffffffffu, l1, 1);
    l1 += __shfl_xor_sync(0xffffffffu, l1, 2);
    const float inv0 = 1.f / l0, inv1 = 1.f / l1;

    #pragma unroll
    for (int nd = 0; nd < 8; nd++) {
        const int cc = nd * 8 + tg * 2;
        unsigned hp;
        hp = pack2h(__float2half(o[nd][0] * inv0), __float2half(o[nd][1] * inv0));
        *(unsigned*)&Oh[gbase + (size_t)rowA * 512 + cc] = hp;
        hp = pack2h(__float2half(o[nd][2] * inv1), __float2half(o[nd][3] * inv1));
        *(unsigned*)&Oh[gbase + (size_t)(rowA + 8) * 512 + cc] = hp;
    }
}

extern "C" void kernel_launch(void* const* d_in, const int* in_sizes, int n_in,
                              void* d_out, int out_size)
{
    const float* q_in  = (const float*)d_in[0];
    const float* kv_in = (const float*)d_in[1];
    const float* Wq    = (const float*)d_in[2];
    const float* Wk    = (const float*)d_in[3];
    const float* Wv    = (const float*)d_in[4];
    const float* Wo    = (const float*)d_in[5];
    const float* bo    = (const float*)d_in[6];
    float* out = (float*)d_out;

    __half *qh, *kvh, *wh, *wl;
    __half *Qh, *Ql, *Kh, *Kl, *Vh, *Vl, *Oh;
    cudaGetSymbolAddress((void**)&qh,  g_qh);
    cudaGetSymbolAddress((void**)&kvh, g_kvh);
    cudaGetSymbolAddress((void**)&wh,  g_wh);  cudaGetSymbolAddress((void**)&wl,  g_wl);
    cudaGetSymbolAddress((void**)&Qh,  g_Qh);  cudaGetSymbolAddress((void**)&Ql,  g_Ql);
    cudaGetSymbolAddress((void**)&Kh,  g_Kh);  cudaGetSymbolAddress((void**)&Kl,  g_Kl);
    cudaGetSymbolAddress((void**)&Vh,  g_Vh);  cudaGetSymbolAddress((void**)&Vl,  g_Vl);
    cudaGetSymbolAddress((void**)&Oh,  g_Oh);

    cudaFuncSetAttribute(gemm_fp16_kernel<1>, cudaFuncAttributeMaxDynamicSharedMemorySize, SMEM_DENSE);
    cudaFuncSetAttribute(gemm_fp16_kernel<0>, cudaFuncAttributeMaxDynamicSharedMemorySize, SMEM_DENSE);
    cudaFuncSetAttribute(flash_kernel,        cudaFuncAttributeMaxDynamicSharedMemorySize, SMEM_FLASH);

    const dim3 ggrid(512 / 128, NTOK / 128, 1);

    cvt_kernel<<<(NELEM / 4 + 255) / 256, 256>>>(q_in,  qh,  NELEM / 4);
    cvt_kernel<<<(NELEM / 4 + 255) / 256, 256>>>(kv_in, kvh, NELEM / 4);
    split4_kernel<<<dim3(WELEM / 4 / 256, 1, 4), 256>>>(Wq, Wk, Wv, Wo, wh, wl);

    gemm_fp16_kernel<1><<<ggrid, 256, SMEM_DENSE>>>(qh,  wh,             wl,             nullptr, Qh, Ql, nullptr, 1.f);
    gemm_fp16_kernel<1><<<ggrid, 256, SMEM_DENSE>>>(kvh, wh + WELEM,     wl + WELEM,     nullptr, Kh, Kl, nullptr, 1.f);
    gemm_fp16_kernel<1><<<ggrid, 256, SMEM_DENSE>>>(kvh, wh + 2 * WELEM, wl + 2 * WELEM, nullptr, Vh, Vl, nullptr, 1.f);

    flash_kernel<<<dim3(4, 256), 256, SMEM_FLASH>>>(Qh, Ql, Kh, Kl, Vh, Vl, Oh);

    gemm_fp16_kernel<0><<<ggrid, 256, SMEM_DENSE>>>(Oh, wh + 3 * WELEM, wl + 3 * WELEM, out, nullptr, nullptr, bo, 1.f);
}

// round 11
// speedup vs baseline: 1.3803x; 1.1487x over previous
#include <cuda_runtime.h>
#include <cuda_fp16.h>
#include <cstdint>

// ----------------------------------------------------------------------------
// CrossAttention, fp16 2-MMA scheme. R11:
//  - Q stored hi-only -> flash QK is 2-term (Qh*Kh + Qh*Kl); Ql eliminated.
//  - Dense GEMM BK=64 (half the barrier cadence), 2-stage cp.async.
//  - cvt launches merged.
// ----------------------------------------------------------------------------

namespace {
constexpr int NTOK = 16384;
constexpr int DMODEL = 512;
constexpr int NELEM = NTOK * DMODEL;
constexpr int WELEM = DMODEL * DMODEL;
constexpr float SCALE = 0.125f;

// dense smem (elements): A 128x64 (stride 72), B 64x128 hi+lo (stride 136)
constexpr int APAD = 72;
constexpr int BPAD = 136;
constexpr int ASZ = 128 * APAD;                  // 9216
constexpr int BSZ = 64 * BPAD;                   // 8704
constexpr int STG = ASZ + 2 * BSZ;               // 26624 elems
constexpr int SMEM_DENSE = 2 * STG * 2;          // 106496 bytes (2 stages)

constexpr int FARR = 64 * 72;
constexpr int FSTG = 4 * FARR;                   // Kh|Kl|Vh|Vl
constexpr int SMEM_FLASH = 2 * FSTG * 2;         // 73728 bytes
}

__device__ __half g_qh[NELEM];                   // q_in  hi
__device__ __half g_kvh[NELEM];                  // kv_in hi
__device__ __half g_wh[4 * WELEM], g_wl[4 * WELEM];
__device__ __half g_Qh[NELEM];
__device__ __half g_Kh[NELEM], g_Kl[NELEM];
__device__ __half g_Vh[NELEM], g_Vl[NELEM];
__device__ __half g_Oh[NELEM];

__device__ __forceinline__ void mma16816(float* d, const unsigned* a, const unsigned* b) {
    asm("mma.sync.aligned.m16n8k16.row.col.f32.f16.f16.f32 "
        "{%0,%1,%2,%3},{%4,%5,%6,%7},{%8,%9},{%0,%1,%2,%3};\n"
        : "+f"(d[0]), "+f"(d[1]), "+f"(d[2]), "+f"(d[3])
        : "r"(a[0]), "r"(a[1]), "r"(a[2]), "r"(a[3]), "r"(b[0]), "r"(b[1]));
}
__device__ __forceinline__ unsigned smem_u32(const void* p) {
    return (unsigned)__cvta_generic_to_shared(p);
}
__device__ __forceinline__ void ldsm_x4(unsigned* r, unsigned addr) {
    asm volatile("ldmatrix.sync.aligned.m8n8.x4.shared.b16 {%0,%1,%2,%3}, [%4];"
                 : "=r"(r[0]), "=r"(r[1]), "=r"(r[2]), "=r"(r[3]) : "r"(addr));
}
__device__ __forceinline__ void ldsm_x4_t(unsigned* r, unsigned addr) {
    asm volatile("ldmatrix.sync.aligned.m8n8.x4.trans.shared.b16 {%0,%1,%2,%3}, [%4];"
                 : "=r"(r[0]), "=r"(r[1]), "=r"(r[2]), "=r"(r[3]) : "r"(addr));
}
__device__ __forceinline__ void cp16(unsigned dst, const void* src) {
    asm volatile("cp.async.cg.shared.global [%0], [%1], 16;\n" :: "r"(dst), "l"(src));
}
__device__ __forceinline__ void cp_commit() { asm volatile("cp.async.commit_group;\n" ::: "memory"); }
__device__ __forceinline__ void cp_wait0()  { asm volatile("cp.async.wait_group 0;\n" ::: "memory"); }
__device__ __forceinline__ void cp_wait1()  { asm volatile("cp.async.wait_group 1;\n" ::: "memory"); }

__device__ __forceinline__ unsigned pack2h(__half x, __half y) {
    __half2 t = __halves2half2(x, y);
    return *reinterpret_cast<unsigned*>(&t);
}
__device__ __forceinline__ void split_pack2h(float x, float y, unsigned& hp, unsigned& lp) {
    __half hx = __float2half(x), hy = __float2half(y);
    __half lx = __float2half(x - __half2float(hx));
    __half ly = __float2half(y - __half2float(hy));
    hp = pack2h(hx, hy);
    lp = pack2h(ly, ly);   // placeholder, overwritten below
    lp = pack2h(lx, ly);
}

// fp32 -> fp16 hi; z=0: q_in, z=1: kv_in
__global__ __launch_bounds__(256)
void cvt2_kernel(const float* __restrict__ q_in, const float* __restrict__ kv_in,
                 __half* __restrict__ qh, __half* __restrict__ kvh, int n4)
{
    const float* src = blockIdx.z ? kv_in : q_in;
    __half* dh = blockIdx.z ? kvh : qh;
    int i = blockIdx.x * blockDim.x + threadIdx.x;
    if (i >= n4) return;
    float4 v = reinterpret_cast<const float4*>(src)[i];
    unsigned h01 = pack2h(__float2half(v.x), __float2half(v.y));
    unsigned h23 = pack2h(__float2half(v.z), __float2half(v.w));
    uint2 hv{h01, h23};
    reinterpret_cast<uint2*>(dh)[i] = hv;
}

// weights: fp32 -> fp16 hi + lo; z selects weight
__global__ __launch_bounds__(256)
void split4_kernel(const float* __restrict__ W0, const float* __restrict__ W1,
                   const float* __restrict__ W2, const float* __restrict__ W3,
                   __half* __restrict__ dh, __half* __restrict__ dl)
{
    const int z = blockIdx.z;
    const float* src = (z == 0) ? W0 : (z == 1) ? W1 : (z == 2) ? W2 : W3;
    __half* h = dh + (size_t)z * WELEM;
    __half* l = dl + (size_t)z * WELEM;
    int i = blockIdx.x * blockDim.x + threadIdx.x;
    if (i >= WELEM / 4) return;
    float4 v = reinterpret_cast<const float4*>(src)[i];
    unsigned h01, l01, h23, l23;
    split_pack2h(v.x, v.y, h01, l01);
    split_pack2h(v.z, v.w, h23, l23);
    uint2 hv{h01, h23}, lv{l01, l23};
    reinterpret_cast<uint2*>(h)[i] = hv;
    reinterpret_cast<uint2*>(l)[i] = lv;
}

// ----------------------------------------------------------------------------
// Dense GEMM: C = Ah@Bh + Ah@Bl (+bias). 128x128 tile, BK=64, 2-stage cp.async.
// OUT_MODE: 0 = fp32 + bias, 1 = fp16 hi+lo pair, 2 = fp16 hi only.
// ----------------------------------------------------------------------------
template <int OUT_MODE>
__global__ __launch_bounds__(256)
void gemm_fp16_kernel(const __half* __restrict__ Ah,
                      const __half* __restrict__ Bh, const __half* __restrict__ Bl,
                      float* __restrict__ Cf,
                      __half* __restrict__ Ch, __half* __restrict__ Cl,
                      const float* __restrict__ bias)
{
    extern __shared__ __half sm[];

    const int tid  = threadIdx.x;
    const int lane = tid & 31, warp = tid >> 5;
    const int wm = warp >> 2, wn = warp & 3;
    const int g  = lane >> 2, tg = lane & 3;
    const int lrow = lane & 7, lsel = lane >> 3;
    const int blockM = blockIdx.y * 128, blockN = blockIdx.x * 128;

    float acc[4][4][4];
    #pragma unroll
    for (int mt = 0; mt < 4; mt++)
        #pragma unroll
        for (int nt = 0; nt < 4; nt++)
            #pragma unroll
            for (int i = 0; i < 4; i++) acc[mt][nt][i] = 0.f;

    auto load_tile = [&](int kt, int s) {
        __half* base = sm + s * STG;
        // A: 128 rows x 64 halves
        #pragma unroll
        for (int j = 0; j < 4; j++) {
            const int idx = tid + j * 256;
            const int row = idx >> 3, c8 = (idx & 7) * 8;
            cp16(smem_u32(base + row * APAD + c8),
                 Ah + (size_t)(blockM + row) * 512 + kt * 64 + c8);
        }
        // B hi+lo: 64 k-rows x 128 halves
        #pragma unroll
        for (int j = 0; j < 4; j++) {
            const int idx = tid + j * 256;
            const int k = idx >> 4, c8 = (idx & 15) * 8;
            const size_t go = (size_t)(kt * 64 + k) * 512 + blockN + c8;
            cp16(smem_u32(base + ASZ + k * BPAD + c8),       Bh + go);
            cp16(smem_u32(base + ASZ + BSZ + k * BPAD + c8), Bl + go);
        }
    };

    load_tile(0, 0);
    cp_commit();

    for (int kt = 0; kt < 8; kt++) {
        cp_wait0();
        __syncthreads();
        if (kt < 7) { load_tile(kt + 1, (kt + 1) & 1); cp_commit(); }

        const __half* base = sm + (kt & 1) * STG;
        #pragma unroll
        for (int kk = 0; kk < 64; kk += 16) {
            unsigned ah[4][4], bh[2][4], bl[2][4];
            #pragma unroll
            for (int mt = 0; mt < 4; mt++) {
                const int r0 = wm * 64 + mt * 16;
                const unsigned ea = smem_u32(base + (r0 + (lsel & 1) * 8 + lrow) * APAD
                                             + kk + (lsel >> 1) * 8);
                ldsm_x4(ah[mt], ea);
            }
            #pragma unroll
            for (int ntp = 0; ntp < 2; ntp++) {
                const int n0 = wn * 32 + ntp * 16;
                const unsigned eb = smem_u32(base + ASZ
                                             + (kk + (lsel & 1) * 8 + lrow) * BPAD
                                             + n0 + (lsel >> 1) * 8);
                ldsm_x4_t(bh[ntp], eb);
                ldsm_x4_t(bl[ntp], eb + BSZ * 2);
            }
            #pragma unroll
            for (int mt = 0; mt < 4; mt++)
                #pragma unroll
                for (int nt = 0; nt < 4; nt++)
                    mma16816(acc[mt][nt], ah[mt], &bh[nt >> 1][(nt & 1) * 2]);
            #pragma unroll
            for (int mt = 0; mt < 4; mt++)
                #pragma unroll
                for (int nt = 0; nt < 4; nt++)
                    mma16816(acc[mt][nt], ah[mt], &bl[nt >> 1][(nt & 1) * 2]);
        }
    }

    #pragma unroll
    for (int mt = 0; mt < 4; mt++)
        #pragma unroll
        for (int nt = 0; nt < 4; nt++) {
            const int r  = blockM + wm * 64 + mt * 16 + g;
            const int cc = blockN + wn * 32 + nt * 8 + tg * 2;
            const float v0 = acc[mt][nt][0];
            const float v1 = acc[mt][nt][1];
            const float v2 = acc[mt][nt][2];
            const float v3 = acc[mt][nt][3];
            if (OUT_MODE == 1) {
                unsigned hp, lp;
                split_pack2h(v0, v1, hp, lp);
                *(unsigned*)&Ch[(size_t)r * 512 + cc] = hp;
                *(unsigned*)&Cl[(size_t)r * 512 + cc] = lp;
                split_pack2h(v2, v3, hp, lp);
                *(unsigned*)&Ch[(size_t)(r + 8) * 512 + cc] = hp;
                *(unsigned*)&Cl[(size_t)(r + 8) * 512 + cc] = lp;
            } else if (OUT_MODE == 2) {
                *(unsigned*)&Ch[(size_t)r * 512 + cc]       = pack2h(__float2half(v0), __float2half(v1));
                *(unsigned*)&Ch[(size_t)(r + 8) * 512 + cc] = pack2h(__float2half(v2), __float2half(v3));
            } else {
                const float b0 = bias[cc], b1 = bias[cc + 1];
                Cf[(size_t)r * 512 + cc]           = v0 + b0;
                Cf[(size_t)r * 512 + cc + 1]       = v1 + b1;
                Cf[(size_t)(r + 8) * 512 + cc]     = v2 + b0;
                Cf[(size_t)(r + 8) * 512 + cc + 1] = v3 + b1;
            }
        }
}

// ----------------------------------------------------------------------------
// Flash attention: QK 2-term (Qh*Kh + Qh*Kl), post-MMA scale, PV 2-term,
// O hi-only. cp.async double-buffered K/V staging.
// ----------------------------------------------------------------------------
__global__ __launch_bounds__(256)
void flash_kernel(const __half* __restrict__ Qh,
                  const __half* __restrict__ Kh, const __half* __restrict__ Kl,
                  const __half* __restrict__ Vh, const __half* __restrict__ Vl,
                  __half* __restrict__ Oh)
{
    extern __shared__ __half fsm[];

    const int z = blockIdx.y;
    const long long zo = z >> 3, zi = z & 7;
    const size_t gbase = (size_t)zo * 512 * 512 + (size_t)zi * 64;

    const int tid  = threadIdx.x;
    const int lane = tid & 31, warp = tid >> 5;
    const int g = lane >> 2, tg = lane & 3;
    const int lrow = lane & 7, lsel = lane >> 3;
    const int rowA = blockIdx.x * 128 + warp * 16 + g;

    unsigned qh[4][4];
    #pragma unroll
    for (int kc = 0; kc < 4; kc++) {
        const int c = kc * 16 + tg * 2;
        qh[kc][0] = *(const unsigned*)&Qh[gbase + (size_t)rowA * 512 + c];
        qh[kc][1] = *(const unsigned*)&Qh[gbase + (size_t)(rowA + 8) * 512 + c];
        qh[kc][2] = *(const unsigned*)&Qh[gbase + (size_t)rowA * 512 + c + 8];
        qh[kc][3] = *(const unsigned*)&Qh[gbase + (size_t)(rowA + 8) * 512 + c + 8];
    }

    auto load_kv = [&](int kt, int s) {
        __half* st = fsm + s * FSTG;
        #pragma unroll
        for (int j = 0; j < 2; j++) {
            const int idx = tid + j * 256;
            const int row = idx >> 3, q = (idx & 7) * 8;
            const size_t go = gbase + (size_t)(kt * 64 + row) * 512 + q;
            const unsigned so = row * 72 + q;
            cp16(smem_u32(st + so),            Kh + go);
            cp16(smem_u32(st + FARR + so),     Kl + go);
            cp16(smem_u32(st + 2 * FARR + so), Vh + go);
            cp16(smem_u32(st + 3 * FARR + so), Vl + go);
        }
    };

    float o[8][4];
    #pragma unroll
    for (int nd = 0; nd < 8; nd++)
        #pragma unroll
        for (int i = 0; i < 4; i++) o[nd][i] = 0.f;
    float m0 = -1e30f, m1 = -1e30f, l0 = 0.f, l1 = 0.f;

    load_kv(0, 0); cp_commit();
    load_kv(1, 1); cp_commit();

    for (int kt = 0; kt < 8; kt++) {
        const int s = kt & 1;
        if (kt < 7) cp_wait1(); else cp_wait0();
        __syncthreads();

        const __half* sKh = fsm + s * FSTG;
        const __half* sKl = sKh + FARR;
        const __half* sVh = sKh + 2 * FARR;
        const __half* sVl = sKh + 3 * FARR;

        float sx[8][4];
        #pragma unroll
        for (int nt = 0; nt < 8; nt++)
            #pragma unroll
            for (int i = 0; i < 4; i++) sx[nt][i] = 0.f;

        #pragma unroll
        for (int kc = 0; kc < 4; kc++) {
            const int c0 = kc * 16;
            #pragma unroll
            for (int ntp = 0; ntp < 4; ntp++) {
                const int n0 = ntp * 16;
                unsigned bh4[4], bl4[4];
                const unsigned ea = smem_u32(sKh + (n0 + (lsel >> 1) * 8 + lrow) * 72 + c0 + (lsel & 1) * 8);
                const unsigned el = smem_u32(sKl + (n0 + (lsel >> 1) * 8 + lrow) * 72 + c0 + (lsel & 1) * 8);
                ldsm_x4(bh4, ea);
                ldsm_x4(bl4, el);
                mma16816(sx[2 * ntp],     qh[kc], bh4);
                mma16816(sx[2 * ntp + 1], qh[kc], bh4 + 2);
                mma16816(sx[2 * ntp],     qh[kc], bl4);
                mma16816(sx[2 * ntp + 1], qh[kc], bl4 + 2);
            }
        }

        #pragma unroll
        for (int nt = 0; nt < 8; nt++)
            #pragma unroll
            for (int i = 0; i < 4; i++) sx[nt][i] *= SCALE;

        float r0 = -1e30f, r1 = -1e30f;
        #pragma unroll
        for (int nt = 0; nt < 8; nt++) {
            r0 = fmaxf(r0, fmaxf(sx[nt][0], sx[nt][1]));
            r1 = fmaxf(r1, fmaxf(sx[nt][2], sx[nt][3]));
        }
        r0 = fmaxf(r0, __shfl_xor_sync(0xffffffffu, r0, 1));
        r0 = fmaxf(r0, __shfl_xor_sync(0xffffffffu, r0, 2));
        r1 = fmaxf(r1, __shfl_xor_sync(0xffffffffu, r1, 1));
        r1 = fmaxf(r1, __shfl_xor_sync(0xffffffffu, r1, 2));
        const float m0n = fmaxf(m0, r0), m1n = fmaxf(m1, r1);
        const float a0 = __expf(m0 - m0n), a1 = __expf(m1 - m1n);

        float ps0 = 0.f, ps1 = 0.f;
        #pragma unroll
        for (int nt = 0; nt < 8; nt++) {
            sx[nt][0] = __expf(sx[nt][0] - m0n);
            sx[nt][1] = __expf(sx[nt][1] - m0n);
            sx[nt][2] = __expf(sx[nt][2] - m1n);
            sx[nt][3] = __expf(sx[nt][3] - m1n);
            ps0 += sx[nt][0] + sx[nt][1];
            ps1 += sx[nt][2] + sx[nt][3];
        }
        m0 = m0n; m1 = m1n;
        l0 = l0 * a0 + ps0;
        l1 = l1 * a1 + ps1;
        #pragma unroll
        for (int nd = 0; nd < 8; nd++) {
            o[nd][0] *= a0; o[nd][1] *= a0;
            o[nd][2] *= a1; o[nd][3] *= a1;
        }

        #pragma unroll
        for (int kc = 0; kc < 4; kc++) {
            const int c0 = kc * 16;
            unsigned pa[4];
            pa[0] = pack2h(__float2half(sx[2 * kc][0]),     __float2half(sx[2 * kc][1]));
            pa[1] = pack2h(__float2half(sx[2 * kc][2]),     __float2half(sx[2 * kc][3]));
            pa[2] = pack2h(__float2half(sx[2 * kc + 1][0]), __float2half(sx[2 * kc + 1][1]));
            pa[3] = pack2h(__float2half(sx[2 * kc + 1][2]), __float2half(sx[2 * kc + 1][3]));
            #pragma unroll
            for (int ndp = 0; ndp < 4; ndp++) {
                const int d0 = ndp * 16;
                unsigned vh4[4], vl4[4];
                const unsigned ea = smem_u32(sVh + (c0 + (lsel & 1) * 8 + lrow) * 72 + d0 + (lsel >> 1) * 8);
                const unsigned el = smem_u32(sVl + (c0 + (lsel & 1) * 8 + lrow) * 72 + d0 + (lsel >> 1) * 8);
                ldsm_x4_t(vh4, ea);
                ldsm_x4_t(vl4, el);
                mma16816(o[2 * ndp],     pa, vh4);
                mma16816(o[2 * ndp + 1], pa, vh4 + 2);
                mma16816(o[2 * ndp],     pa, vl4);
                mma16816(o[2 * ndp + 1], pa, vl4 + 2);
            }
        }
        __syncthreads();
        if (kt + 2 < 8) { load_kv(kt + 2, s); cp_commit(); }
    }

    l0 += __shfl_xor_sync(0xffffffffu, l0, 1);
    l0 += __shfl_xor_sync(0xffffffffu, l0, 2);
    l1 += __shfl_xor_sync(0xffffffffu, l1, 1);
    l1 += __shfl_xor_sync(0xffffffffu, l1, 2);
    const float inv0 = 1.f / l0, inv1 = 1.f / l1;

    #pragma unroll
    for (int nd = 0; nd < 8; nd++) {
        const int cc = nd * 8 + tg * 2;
        unsigned hp;
        hp = pack2h(__float2half(o[nd][0] * inv0), __float2half(o[nd][1] * inv0));
        *(unsigned*)&Oh[gbase + (size_t)rowA * 512 + cc] = hp;
        hp = pack2h(__float2half(o[nd][2] * inv1), __float2half(o[nd][3] * inv1));
        *(unsigned*)&Oh[gbase + (size_t)(rowA + 8) * 512 + cc] = hp;
    }
}

extern "C" void kernel_launch(void* const* d_in, const int* in_sizes, int n_in,
                              void* d_out, int out_size)
{
    const float* q_in  = (const float*)d_in[0];
    const float* kv_in = (const float*)d_in[1];
    const float* Wq    = (const float*)d_in[2];
    const float* Wk    = (const float*)d_in[3];
    const float* Wv    = (const float*)d_in[4];
    const float* Wo    = (const float*)d_in[5];
    const float* bo    = (const float*)d_in[6];
    float* out = (float*)d_out;

    __half *qh, *kvh, *wh, *wl;
    __half *Qh, *Kh, *Kl, *Vh, *Vl, *Oh;
    cudaGetSymbolAddress((void**)&qh,  g_qh);
    cudaGetSymbolAddress((void**)&kvh, g_kvh);
    cudaGetSymbolAddress((void**)&wh,  g_wh);  cudaGetSymbolAddress((void**)&wl,  g_wl);
    cudaGetSymbolAddress((void**)&Qh,  g_Qh);
    cudaGetSymbolAddress((void**)&Kh,  g_Kh);  cudaGetSymbolAddress((void**)&Kl,  g_Kl);
    cudaGetSymbolAddress((void**)&Vh,  g_Vh);  cudaGetSymbolAddress((void**)&Vl,  g_Vl);
    cudaGetSymbolAddress((void**)&Oh,  g_Oh);

    cudaFuncSetAttribute(gemm_fp16_kernel<0>, cudaFuncAttributeMaxDynamicSharedMemorySize, SMEM_DENSE);
    cudaFuncSetAttribute(gemm_fp16_kernel<1>, cudaFuncAttributeMaxDynamicSharedMemorySize, SMEM_DENSE);
    cudaFuncSetAttribute(gemm_fp16_kernel<2>, cudaFuncAttributeMaxDynamicSharedMemorySize, SMEM_DENSE);
    cudaFuncSetAttribute(flash_kernel,        cudaFuncAttributeMaxDynamicSharedMemorySize, SMEM_FLASH);

    const dim3 ggrid(512 / 128, NTOK / 128, 1);

    // 1: input converts (z: 0=q, 1=kv)
    cvt2_kernel<<<dim3((NELEM / 4 + 255) / 256, 1, 2), 256>>>(q_in, kv_in, qh, kvh, NELEM / 4);
    // 2: weight splits
    split4_kernel<<<dim3(WELEM / 4 / 256, 1, 4), 256>>>(Wq, Wk, Wv, Wo, wh, wl);

    // 3-5: projections (Q hi-only)
    gemm_fp16_kernel<2><<<ggrid, 256, SMEM_DENSE>>>(qh,  wh,             wl,             nullptr, Qh, nullptr, nullptr);
    gemm_fp16_kernel<1><<<ggrid, 256, SMEM_DENSE>>>(kvh, wh + WELEM,     wl + WELEM,     nullptr, Kh, Kl, nullptr);
    gemm_fp16_kernel<1><<<ggrid, 256, SMEM_DENSE>>>(kvh, wh + 2 * WELEM, wl + 2 * WELEM, nullptr, Vh, Vl, nullptr);

    // 6: fused flash attention (lands in ncu -s 5 slot)
    flash_kernel<<<dim3(4, 256), 256, SMEM_FLASH>>>(Qh, Kh, Kl, Vh, Vl, Oh);

    // 7: output projection + bias
    gemm_fp16_kernel<0><<<ggrid, 256, SMEM_DENSE>>>(Oh, wh + 3 * WELEM, wl + 3 * WELEM, out, nullptr, nullptr, bo);
}

// round 12
// speedup vs baseline: 2.1940x; 1.5895x over previous
#include <cuda_runtime.h>
#include <cuda_fp16.h>
#include <cstdint>

// ----------------------------------------------------------------------------
// CrossAttention, pure-fp16 single-MMA pipeline (error budget spent: measured
// per-rounding ~1.8e-4 RSS; predicted total ~6.5e-4 < 1e-3).
// Dense GEMMs: 128x128 tile, BK=64, 2-stage cp.async, single-term Ah@Bh.
// Flash: QK 1-term (Q pre-scaled by 0.125 exactly), PV 1-term.
// ----------------------------------------------------------------------------

namespace {
constexpr int NTOK = 16384;
constexpr int DMODEL = 512;
constexpr int NELEM = NTOK * DMODEL;
constexpr int WELEM = DMODEL * DMODEL;

constexpr int APAD = 72;
constexpr int BPAD = 136;
constexpr int ASZ = 128 * APAD;                  // 9216
constexpr int BSZ = 64 * BPAD;                   // 8704
constexpr int STG = ASZ + BSZ;                   // 17920 elems
constexpr int SMEM_DENSE = 2 * STG * 2;          // 71680 bytes

constexpr int FARR = 64 * 72;
constexpr int FSTG = 2 * FARR;                   // K|V
constexpr int SMEM_FLASH = 2 * FSTG * 2;         // 36864 bytes
}

__device__ __half g_qh[NELEM];
__device__ __half g_kvh[NELEM];
__device__ __half g_wh[4 * WELEM];
__device__ __half g_Qh[NELEM];                   // pre-scaled by 0.125
__device__ __half g_Kh[NELEM];
__device__ __half g_Vh[NELEM];
__device__ __half g_Oh[NELEM];

__device__ __forceinline__ void mma16816(float* d, const unsigned* a, const unsigned* b) {
    asm("mma.sync.aligned.m16n8k16.row.col.f32.f16.f16.f32 "
        "{%0,%1,%2,%3},{%4,%5,%6,%7},{%8,%9},{%0,%1,%2,%3};\n"
        : "+f"(d[0]), "+f"(d[1]), "+f"(d[2]), "+f"(d[3])
        : "r"(a[0]), "r"(a[1]), "r"(a[2]), "r"(a[3]), "r"(b[0]), "r"(b[1]));
}
__device__ __forceinline__ unsigned smem_u32(const void* p) {
    return (unsigned)__cvta_generic_to_shared(p);
}
__device__ __forceinline__ void ldsm_x4(unsigned* r, unsigned addr) {
    asm volatile("ldmatrix.sync.aligned.m8n8.x4.shared.b16 {%0,%1,%2,%3}, [%4];"
                 : "=r"(r[0]), "=r"(r[1]), "=r"(r[2]), "=r"(r[3]) : "r"(addr));
}
__device__ __forceinline__ void ldsm_x4_t(unsigned* r, unsigned addr) {
    asm volatile("ldmatrix.sync.aligned.m8n8.x4.trans.shared.b16 {%0,%1,%2,%3}, [%4];"
                 : "=r"(r[0]), "=r"(r[1]), "=r"(r[2]), "=r"(r[3]) : "r"(addr));
}
__device__ __forceinline__ void cp16(unsigned dst, const void* src) {
    asm volatile("cp.async.cg.shared.global [%0], [%1], 16;\n" :: "r"(dst), "l"(src));
}
__device__ __forceinline__ void cp_commit() { asm volatile("cp.async.commit_group;\n" ::: "memory"); }
__device__ __forceinline__ void cp_wait0()  { asm volatile("cp.async.wait_group 0;\n" ::: "memory"); }
__device__ __forceinline__ void cp_wait1()  { asm volatile("cp.async.wait_group 1;\n" ::: "memory"); }

__device__ __forceinline__ unsigned pack2h(__half x, __half y) {
    __half2 t = __halves2half2(x, y);
    return *reinterpret_cast<unsigned*>(&t);
}

// fp32 -> fp16; z=0: q_in, z=1: kv_in
__global__ __launch_bounds__(256)
void cvt2_kernel(const float* __restrict__ q_in, const float* __restrict__ kv_in,
                 __half* __restrict__ qh, __half* __restrict__ kvh, int n4)
{
    const float* src = blockIdx.z ? kv_in : q_in;
    __half* dh = blockIdx.z ? kvh : qh;
    int i = blockIdx.x * blockDim.x + threadIdx.x;
    if (i >= n4) return;
    float4 v = reinterpret_cast<const float4*>(src)[i];
    uint2 hv{pack2h(__float2half(v.x), __float2half(v.y)),
             pack2h(__float2half(v.z), __float2half(v.w))};
    reinterpret_cast<uint2*>(dh)[i] = hv;
}

// weights: fp32 -> fp16 hi only; z selects weight
__global__ __launch_bounds__(256)
void cvt4_kernel(const float* __restrict__ W0, const float* __restrict__ W1,
                 const float* __restrict__ W2, const float* __restrict__ W3,
                 __half* __restrict__ dh)
{
    const int z = blockIdx.z;
    const float* src = (z == 0) ? W0 : (z == 1) ? W1 : (z == 2) ? W2 : W3;
    __half* h = dh + (size_t)z * WELEM;
    int i = blockIdx.x * blockDim.x + threadIdx.x;
    if (i >= WELEM / 4) return;
    float4 v = reinterpret_cast<const float4*>(src)[i];
    uint2 hv{pack2h(__float2half(v.x), __float2half(v.y)),
             pack2h(__float2half(v.z), __float2half(v.w))};
    reinterpret_cast<uint2*>(h)[i] = hv;
}

// ----------------------------------------------------------------------------
// Dense GEMM: C = alpha * (A @ B) (+bias). Pure fp16 single-term.
// 128x128 tile, BK=64, 2-stage cp.async.
// OUT_MODE: 0 = fp32 + bias, 2 = fp16 (scaled by alpha).
// ----------------------------------------------------------------------------
template <int OUT_MODE>
__global__ __launch_bounds__(256)
void gemm_fp16_kernel(const __half* __restrict__ Ah, const __half* __restrict__ Bh,
                      float* __restrict__ Cf, __half* __restrict__ Ch,
                      const float* __restrict__ bias, float alpha)
{
    extern __shared__ __half sm[];

    const int tid  = threadIdx.x;
    const int lane = tid & 31, warp = tid >> 5;
    const int wm = warp >> 2, wn = warp & 3;
    const int g  = lane >> 2, tg = lane & 3;
    const int lrow = lane & 7, lsel = lane >> 3;
    const int blockM = blockIdx.y * 128, blockN = blockIdx.x * 128;

    float acc[4][4][4];
    #pragma unroll
    for (int mt = 0; mt < 4; mt++)
        #pragma unroll
        for (int nt = 0; nt < 4; nt++)
            #pragma unroll
            for (int i = 0; i < 4; i++) acc[mt][nt][i] = 0.f;

    auto load_tile = [&](int kt, int s) {
        __half* base = sm + s * STG;
        #pragma unroll
        for (int j = 0; j < 4; j++) {
            const int idx = tid + j * 256;
            const int row = idx >> 3, c8 = (idx & 7) * 8;
            cp16(smem_u32(base + row * APAD + c8),
                 Ah + (size_t)(blockM + row) * 512 + kt * 64 + c8);
        }
        #pragma unroll
        for (int j = 0; j < 4; j++) {
            const int idx = tid + j * 256;
            const int k = idx >> 4, c8 = (idx & 15) * 8;
            cp16(smem_u32(base + ASZ + k * BPAD + c8),
                 Bh + (size_t)(kt * 64 + k) * 512 + blockN + c8);
        }
    };

    load_tile(0, 0);
    cp_commit();

    for (int kt = 0; kt < 8; kt++) {
        cp_wait0();
        __syncthreads();
        if (kt < 7) { load_tile(kt + 1, (kt + 1) & 1); cp_commit(); }

        const __half* base = sm + (kt & 1) * STG;
        #pragma unroll
        for (int kk = 0; kk < 64; kk += 16) {
            unsigned ah[4][4], bh[2][4];
            #pragma unroll
            for (int mt = 0; mt < 4; mt++) {
                const int r0 = wm * 64 + mt * 16;
                const unsigned ea = smem_u32(base + (r0 + (lsel & 1) * 8 + lrow) * APAD
                                             + kk + (lsel >> 1) * 8);
                ldsm_x4(ah[mt], ea);
            }
            #pragma unroll
            for (int ntp = 0; ntp < 2; ntp++) {
                const int n0 = wn * 32 + ntp * 16;
                const unsigned eb = smem_u32(base + ASZ
                                             + (kk + (lsel & 1) * 8 + lrow) * BPAD
                                             + n0 + (lsel >> 1) * 8);
                ldsm_x4_t(bh[ntp], eb);
            }
            #pragma unroll
            for (int mt = 0; mt < 4; mt++)
                #pragma unroll
                for (int nt = 0; nt < 4; nt++)
                    mma16816(acc[mt][nt], ah[mt], &bh[nt >> 1][(nt & 1) * 2]);
        }
    }

    #pragma unroll
    for (int mt = 0; mt < 4; mt++)
        #pragma unroll
        for (int nt = 0; nt < 4; nt++) {
            const int r  = blockM + wm * 64 + mt * 16 + g;
            const int cc = blockN + wn * 32 + nt * 8 + tg * 2;
            const float v0 = acc[mt][nt][0] * alpha;
            const float v1 = acc[mt][nt][1] * alpha;
            const float v2 = acc[mt][nt][2] * alpha;
            const float v3 = acc[mt][nt][3] * alpha;
            if (OUT_MODE == 2) {
                *(unsigned*)&Ch[(size_t)r * 512 + cc]       = pack2h(__float2half(v0), __float2half(v1));
                *(unsigned*)&Ch[(size_t)(r + 8) * 512 + cc] = pack2h(__float2half(v2), __float2half(v3));
            } else {
                const float b0 = bias[cc], b1 = bias[cc + 1];
                Cf[(size_t)r * 512 + cc]           = v0 + b0;
                Cf[(size_t)r * 512 + cc + 1]       = v1 + b1;
                Cf[(size_t)(r + 8) * 512 + cc]     = v2 + b0;
                Cf[(size_t)(r + 8) * 512 + cc + 1] = v3 + b1;
            }
        }
}

// ----------------------------------------------------------------------------
// Flash attention, pure fp16 (Q pre-scaled). cp.async double-buffered K/V.
// ----------------------------------------------------------------------------
__global__ __launch_bounds__(256)
void flash_kernel(const __half* __restrict__ Qh,
                  const __half* __restrict__ Kh, const __half* __restrict__ Vh,
                  __half* __restrict__ Oh)
{
    extern __shared__ __half fsm[];

    const int z = blockIdx.y;
    const long long zo = z >> 3, zi = z & 7;
    const size_t gbase = (size_t)zo * 512 * 512 + (size_t)zi * 64;

    const int tid  = threadIdx.x;
    const int lane = tid & 31, warp = tid >> 5;
    const int g = lane >> 2, tg = lane & 3;
    const int lrow = lane & 7, lsel = lane >> 3;
    const int rowA = blockIdx.x * 128 + warp * 16 + g;

    unsigned qh[4][4];
    #pragma unroll
    for (int kc = 0; kc < 4; kc++) {
        const int c = kc * 16 + tg * 2;
        qh[kc][0] = *(const unsigned*)&Qh[gbase + (size_t)rowA * 512 + c];
        qh[kc][1] = *(const unsigned*)&Qh[gbase + (size_t)(rowA + 8) * 512 + c];
        qh[kc][2] = *(const unsigned*)&Qh[gbase + (size_t)rowA * 512 + c + 8];
        qh[kc][3] = *(const unsigned*)&Qh[gbase + (size_t)(rowA + 8) * 512 + c + 8];
    }

    auto load_kv = [&](int kt, int s) {
        __half* st = fsm + s * FSTG;
        #pragma unroll
        for (int j = 0; j < 2; j++) {
            const int idx = tid + j * 256;
            const int row = idx >> 3, q = (idx & 7) * 8;
            const size_t go = gbase + (size_t)(kt * 64 + row) * 512 + q;
            const unsigned so = row * 72 + q;
            cp16(smem_u32(st + so),        Kh + go);
            cp16(smem_u32(st + FARR + so), Vh + go);
        }
    };

    float o[8][4];
    #pragma unroll
    for (int nd = 0; nd < 8; nd++)
        #pragma unroll
        for (int i = 0; i < 4; i++) o[nd][i] = 0.f;
    float m0 = -1e30f, m1 = -1e30f, l0 = 0.f, l1 = 0.f;

    load_kv(0, 0); cp_commit();
    load_kv(1, 1); cp_commit();

    for (int kt = 0; kt < 8; kt++) {
        const int s = kt & 1;
        if (kt < 7) cp_wait1(); else cp_wait0();
        __syncthreads();

        const __half* sKh = fsm + s * FSTG;
        const __half* sVh = sKh + FARR;

        float sx[8][4];
        #pragma unroll
        for (int nt = 0; nt < 8; nt++)
            #pragma unroll
            for (int i = 0; i < 4; i++) sx[nt][i] = 0.f;

        #pragma unroll
        for (int kc = 0; kc < 4; kc++) {
            const int c0 = kc * 16;
            #pragma unroll
            for (int ntp = 0; ntp < 4; ntp++) {
                const int n0 = ntp * 16;
                unsigned bh4[4];
                const unsigned ea = smem_u32(sKh + (n0 + (lsel >> 1) * 8 + lrow) * 72 + c0 + (lsel & 1) * 8);
                ldsm_x4(bh4, ea);
                mma16816(sx[2 * ntp],     qh[kc], bh4);
                mma16816(sx[2 * ntp + 1], qh[kc], bh4 + 2);
            }
        }

        float r0 = -1e30f, r1 = -1e30f;
        #pragma unroll
        for (int nt = 0; nt < 8; nt++) {
            r0 = fmaxf(r0, fmaxf(sx[nt][0], sx[nt][1]));
            r1 = fmaxf(r1, fmaxf(sx[nt][2], sx[nt][3]));
        }
        r0 = fmaxf(r0, __shfl_xor_sync(0xffffffffu, r0, 1));
        r0 = fmaxf(r0, __shfl_xor_sync(0xffffffffu, r0, 2));
        r1 = fmaxf(r1, __shfl_xor_sync(0xffffffffu, r1, 1));
        r1 = fmaxf(r1, __shfl_xor_sync(0xffffffffu, r1, 2));
        const float m0n = fmaxf(m0, r0), m1n = fmaxf(m1, r1);
        const float a0 = __expf(m0 - m0n), a1 = __expf(m1 - m1n);

        float ps0 = 0.f, ps1 = 0.f;
        #pragma unroll
        for (int nt = 0; nt < 8; nt++) {
            sx[nt][0] = __expf(sx[nt][0] - m0n);
            sx[nt][1] = __expf(sx[nt][1] - m0n);
            sx[nt][2] = __expf(sx[nt][2] - m1n);
            sx[nt][3] = __expf(sx[nt][3] - m1n);
            ps0 += sx[nt][0] + sx[nt][1];
            ps1 += sx[nt][2] + sx[nt][3];
        }
        m0 = m0n; m1 = m1n;
        l0 = l0 * a0 + ps0;
        l1 = l1 * a1 + ps1;
        #pragma unroll
        for (int nd = 0; nd < 8; nd++) {
            o[nd][0] *= a0; o[nd][1] *= a0;
            o[nd][2] *= a1; o[nd][3] *= a1;
        }

        #pragma unroll
        for (int kc = 0; kc < 4; kc++) {
            const int c0 = kc * 16;
            unsigned pa[4];
            pa[0] = pack2h(__float2half(sx[2 * kc][0]),     __float2half(sx[2 * kc][1]));
            pa[1] = pack2h(__float2half(sx[2 * kc][2]),     __float2half(sx[2 * kc][3]));
            pa[2] = pack2h(__float2half(sx[2 * kc + 1][0]), __float2half(sx[2 * kc + 1][1]));
            pa[3] = pack2h(__float2half(sx[2 * kc + 1][2]), __float2half(sx[2 * kc + 1][3]));
            #pragma unroll
            for (int ndp = 0; ndp < 4; ndp++) {
                const int d0 = ndp * 16;
                unsigned vh4[4];
                const unsigned ea = smem_u32(sVh + (c0 + (lsel & 1) * 8 + lrow) * 72 + d0 + (lsel >> 1) * 8);
                ldsm_x4_t(vh4, ea);
                mma16816(o[2 * ndp],     pa, vh4);
                mma16816(o[2 * ndp + 1], pa, vh4 + 2);
            }
        }
        __syncthreads();
        if (kt + 2 < 8) { load_kv(kt + 2, s); cp_commit(); }
    }

    l0 += __shfl_xor_sync(0xffffffffu, l0, 1);
    l0 += __shfl_xor_sync(0xffffffffu, l0, 2);
    l1 += __shfl_xor_sync(0xffffffffu, l1, 1);
    l1 += __shfl_xor_sync(0xffffffffu, l1, 2);
    const float inv0 = 1.f / l0, inv1 = 1.f / l1;

    #pragma unroll
    for (int nd = 0; nd < 8; nd++) {
        const int cc = nd * 8 + tg * 2;
        *(unsigned*)&Oh[gbase + (size_t)rowA * 512 + cc] =
            pack2h(__float2half(o[nd][0] * inv0), __float2half(o[nd][1] * inv0));
        *(unsigned*)&Oh[gbase + (size_t)(rowA + 8) * 512 + cc] =
            pack2h(__float2half(o[nd][2] * inv1), __float2half(o[nd][3] * inv1));
    }
}

extern "C" void kernel_launch(void* const* d_in, const int* in_sizes, int n_in,
                              void* d_out, int out_size)
{
    const float* q_in  = (const float*)d_in[0];
    const float* kv_in = (const float*)d_in[1];
    const float* Wq    = (const float*)d_in[2];
    const float* Wk    = (const float*)d_in[3];
    const float* Wv    = (const float*)d_in[4];
    const float* Wo    = (const float*)d_in[5];
    const float* bo    = (const float*)d_in[6];
    float* out = (float*)d_out;

    __half *qh, *kvh, *wh, *Qh, *Kh, *Vh, *Oh;
    cudaGetSymbolAddress((void**)&qh,  g_qh);
    cudaGetSymbolAddress((void**)&kvh, g_kvh);
    cudaGetSymbolAddress((void**)&wh,  g_wh);
    cudaGetSymbolAddress((void**)&Qh,  g_Qh);
    cudaGetSymbolAddress((void**)&Kh,  g_Kh);
    cudaGetSymbolAddress((void**)&Vh,  g_Vh);
    cudaGetSymbolAddress((void**)&Oh,  g_Oh);

    cudaFuncSetAttribute(gemm_fp16_kernel<0>, cudaFuncAttributeMaxDynamicSharedMemorySize, SMEM_DENSE);
    cudaFuncSetAttribute(gemm_fp16_kernel<2>, cudaFuncAttributeMaxDynamicSharedMemorySize, SMEM_DENSE);
    cudaFuncSetAttribute(flash_kernel,        cudaFuncAttributeMaxDynamicSharedMemorySize, SMEM_FLASH);

    const dim3 ggrid(512 / 128, NTOK / 128, 1);

    // 1: input converts
    cvt2_kernel<<<dim3((NELEM / 4 + 255) / 256, 1, 2), 256>>>(q_in, kv_in, qh, kvh, NELEM / 4);
    // 2: weight converts
    cvt4_kernel<<<dim3(WELEM / 4 / 256, 1, 4), 256>>>(Wq, Wk, Wv, Wo, wh);

    // 3-5: projections (Q pre-scaled by exact 0.125)
    gemm_fp16_kernel<2><<<ggrid, 256, SMEM_DENSE>>>(qh,  wh,             nullptr, Qh, nullptr, 0.125f);
    gemm_fp16_kernel<2><<<ggrid, 256, SMEM_DENSE>>>(kvh, wh + WELEM,     nullptr, Kh, nullptr, 1.f);
    gemm_fp16_kernel<2><<<ggrid, 256, SMEM_DENSE>>>(kvh, wh + 2 * WELEM, nullptr, Vh, nullptr, 1.f);

    // 6: fused flash attention (ncu -s 5 slot)
    flash_kernel<<<dim3(4, 256), 256, SMEM_FLASH>>>(Qh, Kh, Vh, Oh);

    // 7: output projection + bias
    gemm_fp16_kernel<0><<<ggrid, 256, SMEM_DENSE>>>(Oh, wh + 3 * WELEM, out, nullptr, bo, 1.f);
}

// round 13
// speedup vs baseline: 2.3542x; 1.0730x over previous
#include <cuda_runtime.h>
#include <cuda_fp16.h>
#include <cstdint>

// ----------------------------------------------------------------------------
// CrossAttention, pure-fp16 single-MMA pipeline.
// R13: dense GEMM retiled 64x128 CTA / 32x32 warp tiles, __launch_bounds__
// (256,3) -> 3 CTAs/SM (24 warps) to cover HMMA latency. Flash unchanged.
// ----------------------------------------------------------------------------

namespace {
constexpr int NTOK = 16384;
constexpr int DMODEL = 512;
constexpr int NELEM = NTOK * DMODEL;
constexpr int WELEM = DMODEL * DMODEL;

// dense smem: A 64x64 (stride 72), B 64x128 (stride 136)
constexpr int APAD = 72;
constexpr int BPAD = 136;
constexpr int ASZ = 64 * APAD;                   // 4608
constexpr int BSZ = 64 * BPAD;                   // 8704
constexpr int STG = ASZ + BSZ;                   // 13312 elems
constexpr int SMEM_DENSE = 2 * STG * 2;          // 53248 bytes

constexpr int FARR = 64 * 72;
constexpr int FSTG = 2 * FARR;                   // K|V
constexpr int SMEM_FLASH = 2 * FSTG * 2;         // 36864 bytes
}

__device__ __half g_qh[NELEM];
__device__ __half g_kvh[NELEM];
__device__ __half g_wh[4 * WELEM];
__device__ __half g_Qh[NELEM];                   // pre-scaled by 0.125
__device__ __half g_Kh[NELEM];
__device__ __half g_Vh[NELEM];
__device__ __half g_Oh[NELEM];

__device__ __forceinline__ void mma16816(float* d, const unsigned* a, const unsigned* b) {
    asm("mma.sync.aligned.m16n8k16.row.col.f32.f16.f16.f32 "
        "{%0,%1,%2,%3},{%4,%5,%6,%7},{%8,%9},{%0,%1,%2,%3};\n"
        : "+f"(d[0]), "+f"(d[1]), "+f"(d[2]), "+f"(d[3])
        : "r"(a[0]), "r"(a[1]), "r"(a[2]), "r"(a[3]), "r"(b[0]), "r"(b[1]));
}
__device__ __forceinline__ unsigned smem_u32(const void* p) {
    return (unsigned)__cvta_generic_to_shared(p);
}
__device__ __forceinline__ void ldsm_x4(unsigned* r, unsigned addr) {
    asm volatile("ldmatrix.sync.aligned.m8n8.x4.shared.b16 {%0,%1,%2,%3}, [%4];"
                 : "=r"(r[0]), "=r"(r[1]), "=r"(r[2]), "=r"(r[3]) : "r"(addr));
}
__device__ __forceinline__ void ldsm_x4_t(unsigned* r, unsigned addr) {
    asm volatile("ldmatrix.sync.aligned.m8n8.x4.trans.shared.b16 {%0,%1,%2,%3}, [%4];"
                 : "=r"(r[0]), "=r"(r[1]), "=r"(r[2]), "=r"(r[3]) : "r"(addr));
}
__device__ __forceinline__ void cp16(unsigned dst, const void* src) {
    asm volatile("cp.async.cg.shared.global [%0], [%1], 16;\n" :: "r"(dst), "l"(src));
}
__device__ __forceinline__ void cp_commit() { asm volatile("cp.async.commit_group;\n" ::: "memory"); }
__device__ __forceinline__ void cp_wait0()  { asm volatile("cp.async.wait_group 0;\n" ::: "memory"); }
__device__ __forceinline__ void cp_wait1()  { asm volatile("cp.async.wait_group 1;\n" ::: "memory"); }

__device__ __forceinline__ unsigned pack2h(__half x, __half y) {
    __half2 t = __halves2half2(x, y);
    return *reinterpret_cast<unsigned*>(&t);
}

// fp32 -> fp16; z=0: q_in, z=1: kv_in
__global__ __launch_bounds__(256)
void cvt2_kernel(const float* __restrict__ q_in, const float* __restrict__ kv_in,
                 __half* __restrict__ qh, __half* __restrict__ kvh, int n4)
{
    const float* src = blockIdx.z ? kv_in : q_in;
    __half* dh = blockIdx.z ? kvh : qh;
    int i = blockIdx.x * blockDim.x + threadIdx.x;
    if (i >= n4) return;
    float4 v = reinterpret_cast<const float4*>(src)[i];
    uint2 hv{pack2h(__float2half(v.x), __float2half(v.y)),
             pack2h(__float2half(v.z), __float2half(v.w))};
    reinterpret_cast<uint2*>(dh)[i] = hv;
}

// weights: fp32 -> fp16; z selects weight
__global__ __launch_bounds__(256)
void cvt4_kernel(const float* __restrict__ W0, const float* __restrict__ W1,
                 const float* __restrict__ W2, const float* __restrict__ W3,
                 __half* __restrict__ dh)
{
    const int z = blockIdx.z;
    const float* src = (z == 0) ? W0 : (z == 1) ? W1 : (z == 2) ? W2 : W3;
    __half* h = dh + (size_t)z * WELEM;
    int i = blockIdx.x * blockDim.x + threadIdx.x;
    if (i >= WELEM / 4) return;
    float4 v = reinterpret_cast<const float4*>(src)[i];
    uint2 hv{pack2h(__float2half(v.x), __float2half(v.y)),
             pack2h(__float2half(v.z), __float2half(v.w))};
    reinterpret_cast<uint2*>(h)[i] = hv;
}

// ----------------------------------------------------------------------------
// Dense GEMM: C = alpha * (A @ B) (+bias). Pure fp16 single-term.
// CTA tile 64x128, warp grid 2(M)x4(N), warp tile 32x32, BK=64, 2-stage
// cp.async, 3 CTAs/SM.
// OUT_MODE: 0 = fp32 + bias, 2 = fp16 (scaled by alpha).
// ----------------------------------------------------------------------------
template <int OUT_MODE>
__global__ __launch_bounds__(256, 3)
void gemm_fp16_kernel(const __half* __restrict__ Ah, const __half* __restrict__ Bh,
                      float* __restrict__ Cf, __half* __restrict__ Ch,
                      const float* __restrict__ bias, float alpha)
{
    extern __shared__ __half sm[];

    const int tid  = threadIdx.x;
    const int lane = tid & 31, warp = tid >> 5;
    const int wm = warp >> 2, wn = warp & 3;          // 2x4 warps, 32x32 tiles
    const int g  = lane >> 2, tg = lane & 3;
    const int lrow = lane & 7, lsel = lane >> 3;
    const int blockM = blockIdx.y * 64, blockN = blockIdx.x * 128;

    float acc[2][4][4];
    #pragma unroll
    for (int mt = 0; mt < 2; mt++)
        #pragma unroll
        for (int nt = 0; nt < 4; nt++)
            #pragma unroll
            for (int i = 0; i < 4; i++) acc[mt][nt][i] = 0.f;

    auto load_tile = [&](int kt, int s) {
        __half* base = sm + s * STG;
        // A: 64 rows x 64 halves = 512 cp16
        #pragma unroll
        for (int j = 0; j < 2; j++) {
            const int idx = tid + j * 256;
            const int row = idx >> 3, c8 = (idx & 7) * 8;
            cp16(smem_u32(base + row * APAD + c8),
                 Ah + (size_t)(blockM + row) * 512 + kt * 64 + c8);
        }
        // B: 64 k-rows x 128 halves = 1024 cp16
        #pragma unroll
        for (int j = 0; j < 4; j++) {
            const int idx = tid + j * 256;
            const int k = idx >> 4, c8 = (idx & 15) * 8;
            cp16(smem_u32(base + ASZ + k * BPAD + c8),
                 Bh + (size_t)(kt * 64 + k) * 512 + blockN + c8);
        }
    };

    load_tile(0, 0);
    cp_commit();

    for (int kt = 0; kt < 8; kt++) {
        cp_wait0();
        __syncthreads();
        if (kt < 7) { load_tile(kt + 1, (kt + 1) & 1); cp_commit(); }

        const __half* base = sm + (kt & 1) * STG;
        #pragma unroll
        for (int kk = 0; kk < 64; kk += 16) {
            unsigned ah[2][4], bh[2][4];
            #pragma unroll
            for (int mt = 0; mt < 2; mt++) {
                const int r0 = wm * 32 + mt * 16;
                const unsigned ea = smem_u32(base + (r0 + (lsel & 1) * 8 + lrow) * APAD
                                             + kk + (lsel >> 1) * 8);
                ldsm_x4(ah[mt], ea);
            }
            #pragma unroll
            for (int ntp = 0; ntp < 2; ntp++) {
                const int n0 = wn * 32 + ntp * 16;
                const unsigned eb = smem_u32(base + ASZ
                                             + (kk + (lsel & 1) * 8 + lrow) * BPAD
                                             + n0 + (lsel >> 1) * 8);
                ldsm_x4_t(bh[ntp], eb);
            }
            #pragma unroll
            for (int mt = 0; mt < 2; mt++)
                #pragma unroll
                for (int nt = 0; nt < 4; nt++)
                    mma16816(acc[mt][nt], ah[mt], &bh[nt >> 1][(nt & 1) * 2]);
        }
    }

    #pragma unroll
    for (int mt = 0; mt < 2; mt++)
        #pragma unroll
        for (int nt = 0; nt < 4; nt++) {
            const int r  = blockM + wm * 32 + mt * 16 + g;
            const int cc = blockN + wn * 32 + nt * 8 + tg * 2;
            const float v0 = acc[mt][nt][0] * alpha;
            const float v1 = acc[mt][nt][1] * alpha;
            const float v2 = acc[mt][nt][2] * alpha;
            const float v3 = acc[mt][nt][3] * alpha;
            if (OUT_MODE == 2) {
                *(unsigned*)&Ch[(size_t)r * 512 + cc]       = pack2h(__float2half(v0), __float2half(v1));
                *(unsigned*)&Ch[(size_t)(r + 8) * 512 + cc] = pack2h(__float2half(v2), __float2half(v3));
            } else {
                const float b0 = bias[cc], b1 = bias[cc + 1];
                Cf[(size_t)r * 512 + cc]           = v0 + b0;
                Cf[(size_t)r * 512 + cc + 1]       = v1 + b1;
                Cf[(size_t)(r + 8) * 512 + cc]     = v2 + b0;
                Cf[(size_t)(r + 8) * 512 + cc + 1] = v3 + b1;
            }
        }
}

// ----------------------------------------------------------------------------
// Flash attention, pure fp16 (Q pre-scaled). cp.async double-buffered K/V.
// ----------------------------------------------------------------------------
__global__ __launch_bounds__(256)
void flash_kernel(const __half* __restrict__ Qh,
                  const __half* __restrict__ Kh, const __half* __restrict__ Vh,
                  __half* __restrict__ Oh)
{
    extern __shared__ __half fsm[];

    const int z = blockIdx.y;
    const long long zo = z >> 3, zi = z & 7;
    const size_t gbase = (size_t)zo * 512 * 512 + (size_t)zi * 64;

    const int tid  = threadIdx.x;
    const int lane = tid & 31, warp = tid >> 5;
    const int g = lane >> 2, tg = lane & 3;
    const int lrow = lane & 7, lsel = lane >> 3;
    const int rowA = blockIdx.x * 128 + warp * 16 + g;

    unsigned qh[4][4];
    #pragma unroll
    for (int kc = 0; kc < 4; kc++) {
        const int c = kc * 16 + tg * 2;
        qh[kc][0] = *(const unsigned*)&Qh[gbase + (size_t)rowA * 512 + c];
        qh[kc][1] = *(const unsigned*)&Qh[gbase + (size_t)(rowA + 8) * 512 + c];
        qh[kc][2] = *(const unsigned*)&Qh[gbase + (size_t)rowA * 512 + c + 8];
        qh[kc][3] = *(const unsigned*)&Qh[gbase + (size_t)(rowA + 8) * 512 + c + 8];
    }

    auto load_kv = [&](int kt, int s) {
        __half* st = fsm + s * FSTG;
        #pragma unroll
        for (int j = 0; j < 2; j++) {
            const int idx = tid + j * 256;
            const int row = idx >> 3, q = (idx & 7) * 8;
            const size_t go = gbase + (size_t)(kt * 64 + row) * 512 + q;
            const unsigned so = row * 72 + q;
            cp16(smem_u32(st + so),        Kh + go);
            cp16(smem_u32(st + FARR + so), Vh + go);
        }
    };

    float o[8][4];
    #pragma unroll
    for (int nd = 0; nd < 8; nd++)
        #pragma unroll
        for (int i = 0; i < 4; i++) o[nd][i] = 0.f;
    float m0 = -1e30f, m1 = -1e30f, l0 = 0.f, l1 = 0.f;

    load_kv(0, 0); cp_commit();
    load_kv(1, 1); cp_commit();

    for (int kt = 0; kt < 8; kt++) {
        const int s = kt & 1;
        if (kt < 7) cp_wait1(); else cp_wait0();
        __syncthreads();

        const __half* sKh = fsm + s * FSTG;
        const __half* sVh = sKh + FARR;

        float sx[8][4];
        #pragma unroll
        for (int nt = 0; nt < 8; nt++)
            #pragma unroll
            for (int i = 0; i < 4; i++) sx[nt][i] = 0.f;

        #pragma unroll
        for (int kc = 0; kc < 4; kc++) {
            const int c0 = kc * 16;
            #pragma unroll
            for (int ntp = 0; ntp < 4; ntp++) {
                const int n0 = ntp * 16;
                unsigned bh4[4];
                const unsigned ea = smem_u32(sKh + (n0 + (lsel >> 1) * 8 + lrow) * 72 + c0 + (lsel & 1) * 8);
                ldsm_x4(bh4, ea);
                mma16816(sx[2 * ntp],     qh[kc], bh4);
                mma16816(sx[2 * ntp + 1], qh[kc], bh4 + 2);
            }
        }

        float r0 = -1e30f, r1 = -1e30f;
        #pragma unroll
        for (int nt = 0; nt < 8; nt++) {
            r0 = fmaxf(r0, fmaxf(sx[nt][0], sx[nt][1]));
            r1 = fmaxf(r1, fmaxf(sx[nt][2], sx[nt][3]));
        }
        r0 = fmaxf(r0, __shfl_xor_sync(0xffffffffu, r0, 1));
        r0 = fmaxf(r0, __shfl_xor_sync(0xffffffffu, r0, 2));
        r1 = fmaxf(r1, __shfl_xor_sync(0xffffffffu, r1, 1));
        r1 = fmaxf(r1, __shfl_xor_sync(0xffffffffu, r1, 2));
        const float m0n = fmaxf(m0, r0), m1n = fmaxf(m1, r1);
        const float a0 = __expf(m0 - m0n), a1 = __expf(m1 - m1n);

        float ps0 = 0.f, ps1 = 0.f;
        #pragma unroll
        for (int nt = 0; nt < 8; nt++) {
            sx[nt][0] = __expf(sx[nt][0] - m0n);
            sx[nt][1] = __expf(sx[nt][1] - m0n);
            sx[nt][2] = __expf(sx[nt][2] - m1n);
            sx[nt][3] = __expf(sx[nt][3] - m1n);
            ps0 += sx[nt][0] + sx[nt][1];
            ps1 += sx[nt][2] + sx[nt][3];
        }
        m0 = m0n; m1 = m1n;
        l0 = l0 * a0 + ps0;
        l1 = l1 * a1 + ps1;
        #pragma unroll
        for (int nd = 0; nd < 8; nd++) {
            o[nd][0] *= a0; o[nd][1] *= a0;
            o[nd][2] *= a1; o[nd][3] *= a1;
        }

        #pragma unroll
        for (int kc = 0; kc < 4; kc++) {
            const int c0 = kc * 16;
            unsigned pa[4];
            pa[0] = pack2h(__float2half(sx[2 * kc][0]),     __float2half(sx[2 * kc][1]));
            pa[1] = pack2h(__float2half(sx[2 * kc][2]),     __float2half(sx[2 * kc][3]));
            pa[2] = pack2h(__float2half(sx[2 * kc + 1][0]), __float2half(sx[2 * kc + 1][1]));
            pa[3] = pack2h(__float2half(sx[2 * kc + 1][2]), __float2half(sx[2 * kc + 1][3]));
            #pragma unroll
            for (int ndp = 0; ndp < 4; ndp++) {
                const int d0 = ndp * 16;
                unsigned vh4[4];
                const unsigned ea = smem_u32(sVh + (c0 + (lsel & 1) * 8 + lrow) * 72 + d0 + (lsel >> 1) * 8);
                ldsm_x4_t(vh4, ea);
                mma16816(o[2 * ndp],     pa, vh4);
                mma16816(o[2 * ndp + 1], pa, vh4 + 2);
            }
        }
        __syncthreads();
        if (kt + 2 < 8) { load_kv(kt + 2, s); cp_commit(); }
    }

    l0 += __shfl_xor_sync(0xffffffffu, l0, 1);
    l0 += __shfl_xor_sync(0xffffffffu, l0, 2);
    l1 += __shfl_xor_sync(0xffffffffu, l1, 1);
    l1 += __shfl_xor_sync(0xffffffffu, l1, 2);
    const float inv0 = 1.f / l0, inv1 = 1.f / l1;

    #pragma unroll
    for (int nd = 0; nd < 8; nd++) {
        const int cc = nd * 8 + tg * 2;
        *(unsigned*)&Oh[gbase + (size_t)rowA * 512 + cc] =
            pack2h(__float2half(o[nd][0] * inv0), __float2half(o[nd][1] * inv0));
        *(unsigned*)&Oh[gbase + (size_t)(rowA + 8) * 512 + cc] =
            pack2h(__float2half(o[nd][2] * inv1), __float2half(o[nd][3] * inv1));
    }
}

extern "C" void kernel_launch(void* const* d_in, const int* in_sizes, int n_in,
                              void* d_out, int out_size)
{
    const float* q_in  = (const float*)d_in[0];
    const float* kv_in = (const float*)d_in[1];
    const float* Wq    = (const float*)d_in[2];
    const float* Wk    = (const float*)d_in[3];
    const float* Wv    = (const float*)d_in[4];
    const float* Wo    = (const float*)d_in[5];
    const float* bo    = (const float*)d_in[6];
    float* out = (float*)d_out;

    __half *qh, *kvh, *wh, *Qh, *Kh, *Vh, *Oh;
    cudaGetSymbolAddress((void**)&qh,  g_qh);
    cudaGetSymbolAddress((void**)&kvh, g_kvh);
    cudaGetSymbolAddress((void**)&wh,  g_wh);
    cudaGetSymbolAddress((void**)&Qh,  g_Qh);
    cudaGetSymbolAddress((void**)&Kh,  g_Kh);
    cudaGetSymbolAddress((void**)&Vh,  g_Vh);
    cudaGetSymbolAddress((void**)&Oh,  g_Oh);

    cudaFuncSetAttribute(gemm_fp16_kernel<0>, cudaFuncAttributeMaxDynamicSharedMemorySize, SMEM_DENSE);
    cudaFuncSetAttribute(gemm_fp16_kernel<2>, cudaFuncAttributeMaxDynamicSharedMemorySize, SMEM_DENSE);
    cudaFuncSetAttribute(flash_kernel,        cudaFuncAttributeMaxDynamicSharedMemorySize, SMEM_FLASH);

    const dim3 ggrid(512 / 128, NTOK / 64, 1);   // (4, 256)

    // 1: input converts
    cvt2_kernel<<<dim3((NELEM / 4 + 255) / 256, 1, 2), 256>>>(q_in, kv_in, qh, kvh, NELEM / 4);
    // 2: weight converts
    cvt4_kernel<<<dim3(WELEM / 4 / 256, 1, 4), 256>>>(Wq, Wk, Wv, Wo, wh);

    // 3-5: projections (Q pre-scaled by exact 0.125)
    gemm_fp16_kernel<2><<<ggrid, 256, SMEM_DENSE>>>(qh,  wh,             nullptr, Qh, nullptr, 0.125f);
    gemm_fp16_kernel<2><<<ggrid, 256, SMEM_DENSE>>>(kvh, wh + WELEM,     nullptr, Kh, nullptr, 1.f);
    gemm_fp16_kernel<2><<<ggrid, 256, SMEM_DENSE>>>(kvh, wh + 2 * WELEM, nullptr, Vh, nullptr, 1.f);

    // 6: fused flash attention (ncu -s 5 slot)
    flash_kernel<<<dim3(4, 256), 256, SMEM_FLASH>>>(Qh, Kh, Vh, Oh);

    // 7: output projection + bias
    gemm_fp16_kernel<0><<<ggrid, 256, SMEM_DENSE>>>(Oh, wh + 3 * WELEM, out, nullptr, bo, 1.f);
}